// round 3
// baseline (speedup 1.0000x reference)
#include <cuda_runtime.h>
#include <math.h>

#define H       1024
#define DIN     2048
#define KEY_DIM 1024
#define DICT_LEN 16384
#define A2C_H   512
#define N_ACT   1024
#define BB      256
#define FIVE_H  (5*H)
#define EPSN    1e-8f

// ---- output layout (float32, tuple order flattened) ----
#define OFF_A    0
#define OFF_PROB 256
#define OFF_V    512
#define OFF_ENT  768
#define OFF_H    1024
#define OFF_C    (OFF_H + BB*H)
#define OFF_BEST (OFF_C + BB*H)
#define OFF_NK   (OFF_BEST + 256)
#define OFF_NV   (OFF_NK + DICT_LEN*KEY_DIM)

// ---- scratch (static device globals; no allocation allowed) ----
__device__ float g_preact[BB*FIVE_H];
__device__ float g_qinv[BB];
__device__ float g_kinv[DICT_LEN];
__device__ float g_sims[(size_t)DICT_LEN * BB];   // r-major [r][b]
__device__ float g_pval[256 * BB];                // per-chunk partial max [chunk][b]
__device__ int   g_pidx[256 * BB];
__device__ int   g_bestidx[BB];
__device__ float g_ha[BB*A2C_H];
__device__ float g_logits[BB*N_ACT];

__device__ __forceinline__ float sigmoidf_(float x) { return 1.0f / (1.0f + expf(-x)); }

// ---- Threefry-2x32-20 with key (0,1)  (jax.random.key(1)) ----
__device__ __forceinline__ void threefry01(unsigned x0, unsigned x1,
                                           unsigned &o0, unsigned &o1) {
    const unsigned ks0 = 0u, ks1 = 1u, ks2 = 0u ^ 1u ^ 0x1BD11BDAu;
    x0 += ks0; x1 += ks1;
#define ROTL(v,r) (((v) << (r)) | ((v) >> (32 - (r))))
#define RND(r) { x0 += x1; x1 = ROTL(x1, r); x1 ^= x0; }
    RND(13) RND(15) RND(26) RND(6)
    x0 += ks1; x1 += ks2 + 1u;
    RND(17) RND(29) RND(16) RND(24)
    x0 += ks2; x1 += ks0 + 2u;
    RND(13) RND(15) RND(26) RND(6)
    x0 += ks0; x1 += ks1 + 3u;
    RND(17) RND(29) RND(16) RND(24)
    x0 += ks1; x1 += ks2 + 4u;
    RND(13) RND(15) RND(26) RND(6)
    x0 += ks2; x1 += ks0 + 5u;
#undef RND
#undef ROTL
    o0 = x0; o1 = x1;
}

// gumbel value for flat index j in a (256,1024) draw.
// jax >= 0.4.36: jax_threefry_partitionable defaults to True, so random_bits
// uses counter pair (hi32(j), lo32(j)) = (0, j) per element and combines the
// two output lanes with XOR for 32-bit draws.
__device__ __forceinline__ float gumbel_at(int j) {
    unsigned o0, o1;
    threefry01(0u, (unsigned)j, o0, o1);
    unsigned bits = o0 ^ o1;
    float f = __uint_as_float((bits >> 9) | 0x3f800000u) - 1.0f;
    const float TINY = 1.1754943508222875e-38f;
    float u = fmaxf(TINY, f * (1.0f - TINY) + TINY);
    return -logf(-logf(u));
}

// ================= kernels =================

// copy mem_keys->new_keys, mem_vals->new_vals, and key row inv-norms
__global__ __launch_bounds__(128) void k_copy_norm(
    const float* __restrict__ mk, const float* __restrict__ mv,
    float* __restrict__ nk, float* __restrict__ nv) {
    int row = blockIdx.x;
    int t = threadIdx.x;
    const float4* sk = (const float4*)(mk + (size_t)row * KEY_DIM);
    float4* dk = (float4*)(nk + (size_t)row * KEY_DIM);
    const float4* sv = (const float4*)(mv + (size_t)row * H);
    float4* dv = (float4*)(nv + (size_t)row * H);
    float ss = 0.f;
    #pragma unroll
    for (int i = t; i < KEY_DIM/4; i += 128) {
        float4 v = sk[i]; dk[i] = v;
        ss += v.x*v.x + v.y*v.y + v.z*v.z + v.w*v.w;
    }
    #pragma unroll
    for (int i = t; i < H/4; i += 128) dv[i] = sv[i];
    #pragma unroll
    for (int o = 16; o > 0; o >>= 1) ss += __shfl_down_sync(0xffffffffu, ss, o);
    __shared__ float w[4];
    if ((t & 31) == 0) w[t >> 5] = ss;
    __syncthreads();
    if (t == 0) {
        float s = w[0] + w[1] + w[2] + w[3];
        g_kinv[row] = 1.0f / fmaxf(sqrtf(s), EPSN);
    }
}

__global__ __launch_bounds__(128) void k_qnorm(const float* __restrict__ q) {
    int row = blockIdx.x;
    int t = threadIdx.x;
    const float4* sq = (const float4*)(q + (size_t)row * KEY_DIM);
    float ss = 0.f;
    #pragma unroll
    for (int i = t; i < KEY_DIM/4; i += 128) {
        float4 v = sq[i];
        ss += v.x*v.x + v.y*v.y + v.z*v.z + v.w*v.w;
    }
    #pragma unroll
    for (int o = 16; o > 0; o >>= 1) ss += __shfl_down_sync(0xffffffffu, ss, o);
    __shared__ float w[4];
    if ((t & 31) == 0) w[t >> 5] = ss;
    __syncthreads();
    if (t == 0) {
        float s = w[0] + w[1] + w[2] + w[3];
        g_qinv[row] = 1.0f / fmaxf(sqrtf(s), EPSN);
    }
}

// preact[256,5120] = obs@Wi + h@Wh + bi + bh   (combined K = 3072)
__global__ __launch_bounds__(256) void k_preact(
    const float* __restrict__ obs, const float* __restrict__ hin,
    const float* __restrict__ Wi, const float* __restrict__ Wh,
    const float* __restrict__ bi, const float* __restrict__ bh) {
    __shared__ float As[16][128];
    __shared__ float Bs[16][128];
    int n0 = blockIdx.x * 128;
    int m0 = blockIdx.y * 128;
    int t = threadIdx.x;
    int tx = t & 15, ty = t >> 4;
    float acc[8][8];
    #pragma unroll
    for (int i = 0; i < 8; i++)
        #pragma unroll
        for (int j = 0; j < 8; j++) acc[i][j] = 0.f;

    for (int k0 = 0; k0 < DIN + H; k0 += 16) {
        bool first = (k0 < DIN);
        #pragma unroll
        for (int i = 0; i < 2; i++) {
            int id = t * 2 + i;          // 0..511
            int row = id >> 2, kq = id & 3;
            const float* src = first ? (obs + (size_t)(m0+row)*DIN + k0 + kq*4)
                                     : (hin + (size_t)(m0+row)*H + (k0-DIN) + kq*4);
            float4 v = *(const float4*)src;
            As[kq*4+0][row] = v.x; As[kq*4+1][row] = v.y;
            As[kq*4+2][row] = v.z; As[kq*4+3][row] = v.w;
        }
        #pragma unroll
        for (int i = 0; i < 2; i++) {
            int id = t * 2 + i;          // 0..511
            int kk = id >> 5, nq = id & 31;
            const float* src = first ? (Wi + (size_t)(k0+kk)*FIVE_H + n0 + nq*4)
                                     : (Wh + (size_t)(k0-DIN+kk)*FIVE_H + n0 + nq*4);
            *(float4*)&Bs[kk][nq*4] = *(const float4*)src;
        }
        __syncthreads();
        #pragma unroll
        for (int kk = 0; kk < 16; kk++) {
            float a[8], b[8];
            #pragma unroll
            for (int i = 0; i < 8; i++) a[i] = As[kk][ty + i*16];
            #pragma unroll
            for (int j = 0; j < 8; j++) b[j] = Bs[kk][tx + j*16];
            #pragma unroll
            for (int i = 0; i < 8; i++)
                #pragma unroll
                for (int j = 0; j < 8; j++) acc[i][j] += a[i] * b[j];
        }
        __syncthreads();
    }
    #pragma unroll
    for (int i = 0; i < 8; i++) {
        int m = m0 + ty + i*16;
        #pragma unroll
        for (int j = 0; j < 8; j++) {
            int n = n0 + tx + j*16;
            g_preact[(size_t)m*FIVE_H + n] = acc[i][j] + bi[n] + bh[n];
        }
    }
}

// sims tile: 64 mem rows x all 256 queries, K=1024; stores cosine sims r-major
__global__ __launch_bounds__(256) void k_simgemm(
    const float* __restrict__ mk, const float* __restrict__ q) {
    __shared__ float As[16][64];
    __shared__ float Bs[16][256];
    int r0 = blockIdx.x * 64;
    int t = threadIdx.x;
    int tx = t & 15, ty = t >> 4;
    float acc[4][16];
    #pragma unroll
    for (int i = 0; i < 4; i++)
        #pragma unroll
        for (int j = 0; j < 16; j++) acc[i][j] = 0.f;

    for (int k0 = 0; k0 < KEY_DIM; k0 += 16) {
        {
            int row = t >> 2, kq = t & 3;  // 64 rows x 4 float4
            float4 v = *(const float4*)(mk + (size_t)(r0+row)*KEY_DIM + k0 + kq*4);
            As[kq*4+0][row] = v.x; As[kq*4+1][row] = v.y;
            As[kq*4+2][row] = v.z; As[kq*4+3][row] = v.w;
        }
        #pragma unroll
        for (int i = 0; i < 4; i++) {
            int id = t + i*256;            // 0..1023
            int row = id >> 2, kq = id & 3;
            float4 v = *(const float4*)(q + (size_t)row*KEY_DIM + k0 + kq*4);
            Bs[kq*4+0][row] = v.x; Bs[kq*4+1][row] = v.y;
            Bs[kq*4+2][row] = v.z; Bs[kq*4+3][row] = v.w;
        }
        __syncthreads();
        #pragma unroll
        for (int kk = 0; kk < 16; kk++) {
            float a[4], b[16];
            #pragma unroll
            for (int i = 0; i < 4; i++) a[i] = As[kk][ty + i*16];
            #pragma unroll
            for (int j = 0; j < 16; j++) b[j] = Bs[kk][tx + j*16];
            #pragma unroll
            for (int i = 0; i < 4; i++)
                #pragma unroll
                for (int j = 0; j < 16; j++) acc[i][j] += a[i] * b[j];
        }
        __syncthreads();
    }
    float kin[4];
    #pragma unroll
    for (int i = 0; i < 4; i++) kin[i] = g_kinv[r0 + ty + i*16];
    #pragma unroll
    for (int i = 0; i < 4; i++) {
        int r = r0 + ty + i*16;
        #pragma unroll
        for (int j = 0; j < 16; j++) {
            int b_ = tx + j*16;
            g_sims[(size_t)r * BB + b_] = acc[i][j] * kin[i] * g_qinv[b_];
        }
    }
}

// per-chunk argmax: block = 64-row chunk, thread t = query t
__global__ __launch_bounds__(256) void k_chunkmax() {
    int r0 = blockIdx.x * 64;
    int t = threadIdx.x;
    float bv = -3.0e38f;
    int bi_ = 0;
    for (int rr = 0; rr < 64; rr++) {
        int r = r0 + rr;
        float v = g_sims[(size_t)r * BB + t];
        if (v > bv) { bv = v; bi_ = r; }   // ascending r => strict '>' keeps first index
    }
    g_pval[blockIdx.x * BB + t] = bv;
    g_pidx[blockIdx.x * BB + t] = bi_;
}

// final argmax across 256 chunks per query
__global__ __launch_bounds__(256) void k_finalmax() {
    int b_ = blockIdx.x;
    int t = threadIdx.x;
    __shared__ float sv[256];
    __shared__ int   si[256];
    sv[t] = g_pval[t * BB + b_];
    si[t] = g_pidx[t * BB + b_];
    __syncthreads();
    for (int s = 128; s > 0; s >>= 1) {
        if (t < s) {
            if (sv[t+s] > sv[t] || (sv[t+s] == sv[t] && si[t+s] < si[t])) {
                sv[t] = sv[t+s]; si[t] = si[t+s];
            }
        }
        __syncthreads();
    }
    if (t == 0) g_bestidx[b_] = si[0];
}

// gates + DND readout + h_t/c_t + best_mem_id
__global__ __launch_bounds__(256) void k_lstm(
    const float* __restrict__ c_in, const float* __restrict__ mv,
    float* __restrict__ out) {
    int idx = blockIdx.x * 256 + threadIdx.x;   // 0..262143
    int b_ = idx >> 10, j = idx & 1023;
    int best = g_bestidx[b_];
    const float* p = g_preact + (size_t)b_ * FIVE_H;
    float f  = sigmoidf_(p[j]);
    float it = sigmoidf_(p[H + j]);
    float o  = sigmoidf_(p[2*H + j]);
    float r  = sigmoidf_(p[3*H + j]);
    float cn = tanhf(p[4*H + j]);
    float m  = tanhf(mv[(size_t)best * H + j]);
    float ct = f * c_in[idx] + it * cn + r * m;
    float ht = o * tanhf(ct);
    out[OFF_H + idx] = ht;
    out[OFF_C + idx] = ct;
    if (j == 0) out[OFF_BEST + b_] = (float)best;
}

// generic 64x64 tiled fp32 GEMM: C = act(A[MxK] @ B[KxN] + bias)
template<int RELU>
__global__ __launch_bounds__(256) void k_gemm(
    const float* __restrict__ A, const float* __restrict__ Bm,
    const float* __restrict__ bias, float* __restrict__ C,
    int M, int N, int K) {
    __shared__ float As[16][64];
    __shared__ float Bs[16][64];
    int n0 = blockIdx.x * 64;
    int m0 = blockIdx.y * 64;
    int t = threadIdx.x;
    int tx = t & 15, ty = t >> 4;
    float acc[4][4];
    #pragma unroll
    for (int i = 0; i < 4; i++)
        #pragma unroll
        for (int j = 0; j < 4; j++) acc[i][j] = 0.f;
    for (int k0 = 0; k0 < K; k0 += 16) {
        {
            int row = t >> 2, kq = t & 3;
            float4 v = *(const float4*)(A + (size_t)(m0+row)*K + k0 + kq*4);
            As[kq*4+0][row] = v.x; As[kq*4+1][row] = v.y;
            As[kq*4+2][row] = v.z; As[kq*4+3][row] = v.w;
        }
        {
            int kk = t >> 4, nq = t & 15;
            *(float4*)&Bs[kk][nq*4] =
                *(const float4*)(Bm + (size_t)(k0+kk)*N + n0 + nq*4);
        }
        __syncthreads();
        #pragma unroll
        for (int kk = 0; kk < 16; kk++) {
            float a[4], b[4];
            #pragma unroll
            for (int i = 0; i < 4; i++) a[i] = As[kk][ty + i*16];
            #pragma unroll
            for (int j = 0; j < 4; j++) b[j] = Bs[kk][tx + j*16];
            #pragma unroll
            for (int i = 0; i < 4; i++)
                #pragma unroll
                for (int j = 0; j < 4; j++) acc[i][j] += a[i] * b[j];
        }
        __syncthreads();
    }
    #pragma unroll
    for (int i = 0; i < 4; i++) {
        int m = m0 + ty + i*16;
        #pragma unroll
        for (int j = 0; j < 4; j++) {
            int n = n0 + tx + j*16;
            float v = acc[i][j] + bias[n];
            if (RELU) v = fmaxf(v, 0.f);
            C[(size_t)m*N + n] = v;
        }
    }
}

// per-row: log_softmax stats, entropy, critic value, gumbel-argmax sample
__global__ __launch_bounds__(256) void k_final(
    const float* __restrict__ Wc, const float* __restrict__ bc,
    float* __restrict__ out) {
    int b_ = blockIdx.x;
    int t = threadIdx.x;
    __shared__ float sred[256];
    __shared__ float sgv[256];
    __shared__ int   sgi[256];
    const float* lrow = g_logits + (size_t)b_ * N_ACT;
    float l[4];
    #pragma unroll
    for (int k = 0; k < 4; k++) l[k] = lrow[t + k*256];

    // max
    float mx = fmaxf(fmaxf(l[0], l[1]), fmaxf(l[2], l[3]));
    sred[t] = mx; __syncthreads();
    for (int s = 128; s > 0; s >>= 1) {
        if (t < s) sred[t] = fmaxf(sred[t], sred[t+s]);
        __syncthreads();
    }
    mx = sred[0]; __syncthreads();

    // sum exp
    float se = 0.f;
    #pragma unroll
    for (int k = 0; k < 4; k++) se += expf(l[k] - mx);
    sred[t] = se; __syncthreads();
    for (int s = 128; s > 0; s >>= 1) {
        if (t < s) sred[t] += sred[t+s];
        __syncthreads();
    }
    float lse = mx + logf(sred[0]); __syncthreads();

    // entropy
    float ent = 0.f;
    #pragma unroll
    for (int k = 0; k < 4; k++) {
        float lp = l[k] - lse;
        ent += expf(lp) * lp;
    }
    sred[t] = ent; __syncthreads();
    for (int s = 128; s > 0; s >>= 1) {
        if (t < s) sred[t] += sred[t+s];
        __syncthreads();
    }
    float entropy = -sred[0]; __syncthreads();

    // critic value
    const float* ha = g_ha + (size_t)b_ * A2C_H;
    float v = ha[t] * Wc[t] + ha[t + 256] * Wc[t + 256];
    sred[t] = v; __syncthreads();
    for (int s = 128; s > 0; s >>= 1) {
        if (t < s) sred[t] += sred[t+s];
        __syncthreads();
    }
    float vt = sred[0] + bc[0];

    // gumbel-argmax (jax.random.categorical(key(1), log_pi))
    float bv = -3.0e38f; int bn = 0;
    #pragma unroll
    for (int k = 0; k < 4; k++) {
        int n = t + k*256;                 // ascending within thread
        float g = gumbel_at(b_ * N_ACT + n);
        float cand = (l[k] - lse) + g;
        if (cand > bv) { bv = cand; bn = n; }
    }
    sgv[t] = bv; sgi[t] = bn; __syncthreads();
    for (int s = 128; s > 0; s >>= 1) {
        if (t < s) {
            if (sgv[t+s] > sgv[t] || (sgv[t+s] == sgv[t] && sgi[t+s] < sgi[t])) {
                sgv[t] = sgv[t+s]; sgi[t] = sgi[t+s];
            }
        }
        __syncthreads();
    }
    if (t == 0) {
        int nbest = sgi[0];
        out[OFF_A + b_] = (float)nbest;
        out[OFF_PROB + b_] = lrow[nbest] - lse;
        out[OFF_V + b_] = vt;
        out[OFF_ENT + b_] = entropy;
    }
}

// last-write-wins scatter of q_t / c_t into the dict copies
__global__ __launch_bounds__(256) void k_scatter(
    const int* __restrict__ widx, const float* __restrict__ q,
    float* __restrict__ out) {
    int b_ = blockIdx.x;
    __shared__ int target;
    if (threadIdx.x == 0) {
        int idx = widx[b_];
        int last = 1;
        for (int b2 = b_ + 1; b2 < BB; b2++)
            if (widx[b2] == idx) { last = 0; break; }
        target = last ? idx : -1;
    }
    __syncthreads();
    int idx = target;
    if (idx < 0) return;
    int t = threadIdx.x;
    const float4* qs = (const float4*)(q + (size_t)b_ * KEY_DIM);
    const float4* cs = (const float4*)(out + OFF_C + (size_t)b_ * H);
    float4* kd = (float4*)(out + OFF_NK + (size_t)idx * KEY_DIM);
    float4* vd = (float4*)(out + OFF_NV + (size_t)idx * H);
    kd[t] = qs[t];
    vd[t] = cs[t];
}

extern "C" void kernel_launch(void* const* d_in, const int* in_sizes, int n_in,
                              void* d_out, int out_size) {
    const float* obs     = (const float*)d_in[0];
    const float* barcode = (const float*)d_in[1];
    const float* h_in    = (const float*)d_in[2];
    const float* c_in    = (const float*)d_in[3];
    const int*   widx    = (const int*)  d_in[4];
    const float* Wi      = (const float*)d_in[5];
    const float* bi      = (const float*)d_in[6];
    const float* Wh      = (const float*)d_in[7];
    const float* bh      = (const float*)d_in[8];
    const float* mk      = (const float*)d_in[9];
    const float* mv      = (const float*)d_in[10];
    const float* Wa      = (const float*)d_in[11];
    const float* ba      = (const float*)d_in[12];
    const float* Wact    = (const float*)d_in[13];
    const float* bact    = (const float*)d_in[14];
    const float* Wc      = (const float*)d_in[15];
    const float* bc      = (const float*)d_in[16];
    float* out = (float*)d_out;

    float* g_ha_ptr; cudaGetSymbolAddress((void**)&g_ha_ptr, g_ha);
    float* g_logits_ptr; cudaGetSymbolAddress((void**)&g_logits_ptr, g_logits);

    k_copy_norm<<<DICT_LEN, 128>>>(mk, mv, out + OFF_NK, out + OFF_NV);
    k_qnorm<<<BB, 128>>>(barcode);
    k_preact<<<dim3(FIVE_H/128, BB/128), 256>>>(obs, h_in, Wi, Wh, bi, bh);
    k_simgemm<<<DICT_LEN/64, 256>>>(mk, barcode);
    k_chunkmax<<<DICT_LEN/64, 256>>>();
    k_finalmax<<<BB, 256>>>();
    k_lstm<<<BB*H/256, 256>>>(c_in, mv, out);
    k_scatter<<<BB, 256>>>(widx, barcode, out);
    // ha = relu(c_t @ Wa + ba)
    k_gemm<1><<<dim3(A2C_H/64, BB/64), 256>>>(out + OFF_C, Wa, ba, g_ha_ptr,
                                              BB, A2C_H, H);
    // logits = ha @ W_actor + b_actor
    k_gemm<0><<<dim3(N_ACT/64, BB/64), 256>>>(g_ha_ptr, Wact, bact, g_logits_ptr,
                                              BB, N_ACT, A2C_H);
    k_final<<<BB, 256>>>(Wc, bc, out);
}

// round 5
// speedup vs baseline: 2.1090x; 2.1090x over previous
#include <cuda_runtime.h>
#include <cuda_bf16.h>
#include <math.h>
#include <stdint.h>

#define H       1024
#define DIN     2048
#define KEY_DIM 1024
#define DICT_LEN 16384
#define A2C_H   512
#define N_ACT   1024
#define BB      256
#define FIVE_H  (5*H)
#define KTOT    3072
#define EPSN    1e-8f

// ---- output layout (float32, tuple order flattened) ----
#define OFF_A    0
#define OFF_PROB 256
#define OFF_V    512
#define OFF_ENT  768
#define OFF_H    1024
#define OFF_C    (OFF_H + BB*H)
#define OFF_BEST (OFF_C + BB*H)
#define OFF_NK   (OFF_BEST + 256)
#define OFF_NV   (OFF_NK + DICT_LEN*KEY_DIM)

// ---- scratch (static device globals; no allocation allowed) ----
__device__ float g_preact[BB*FIVE_H];
__device__ float g_qinv[BB];
__device__ float g_kinv[DICT_LEN];
__device__ __nv_bfloat16 g_qhi[BB*KEY_DIM];
__device__ __nv_bfloat16 g_qlo[BB*KEY_DIM];
__device__ __nv_bfloat16 g_ahi[BB*KTOT];
__device__ __nv_bfloat16 g_alo[BB*KTOT];
__device__ __nv_bfloat16 g_wthi[(size_t)FIVE_H*KTOT];
__device__ __nv_bfloat16 g_wtlo[(size_t)FIVE_H*KTOT];
__device__ unsigned long long g_ppack[128 * BB];  // [chunk][query]
__device__ int   g_bestidx[BB];
__device__ float g_ha[BB*A2C_H];
__device__ float g_logits[BB*N_ACT];

__device__ __forceinline__ float sigmoidf_(float x) { return 1.0f / (1.0f + expf(-x)); }

__device__ __forceinline__ unsigned float_flip(float f) {
    unsigned u = __float_as_uint(f);
    return (u & 0x80000000u) ? ~u : (u | 0x80000000u);
}

__device__ __forceinline__ unsigned long long pack_vi(float v, int row) {
    return ((unsigned long long)float_flip(v) << 32) |
           (unsigned)(0x7FFFFFFFu - (unsigned)row);
}

// HMMA m16n8k16 bf16, fp32 accum (sm_80 path -> compiles for plain sm_103)
__device__ __forceinline__ void mma_bf16(float* c, const uint32_t* a,
                                         uint32_t b0, uint32_t b1) {
    asm volatile(
        "mma.sync.aligned.m16n8k16.row.col.f32.bf16.bf16.f32 "
        "{%0,%1,%2,%3}, {%4,%5,%6,%7}, {%8,%9}, {%0,%1,%2,%3};\n"
        : "+f"(c[0]), "+f"(c[1]), "+f"(c[2]), "+f"(c[3])
        : "r"(a[0]), "r"(a[1]), "r"(a[2]), "r"(a[3]), "r"(b0), "r"(b1));
}

__device__ __forceinline__ void split_bf16(float v, __nv_bfloat16& hi, __nv_bfloat16& lo) {
    hi = __float2bfloat16(v);
    lo = __float2bfloat16(v - __bfloat162float(hi));
}

// ---- Threefry-2x32-20 with key (0,1)  (jax.random.key(1)) ----
__device__ __forceinline__ void threefry01(unsigned x0, unsigned x1,
                                           unsigned &o0, unsigned &o1) {
    const unsigned ks0 = 0u, ks1 = 1u, ks2 = 0u ^ 1u ^ 0x1BD11BDAu;
    x0 += ks0; x1 += ks1;
#define ROTL(v,r) (((v) << (r)) | ((v) >> (32 - (r))))
#define RND(r) { x0 += x1; x1 = ROTL(x1, r); x1 ^= x0; }
    RND(13) RND(15) RND(26) RND(6)
    x0 += ks1; x1 += ks2 + 1u;
    RND(17) RND(29) RND(16) RND(24)
    x0 += ks2; x1 += ks0 + 2u;
    RND(13) RND(15) RND(26) RND(6)
    x0 += ks0; x1 += ks1 + 3u;
    RND(17) RND(29) RND(16) RND(24)
    x0 += ks1; x1 += ks2 + 4u;
    RND(13) RND(15) RND(26) RND(6)
    x0 += ks2; x1 += ks0 + 5u;
#undef RND
#undef ROTL
    o0 = x0; o1 = x1;
}

// partitionable threefry: counter (0, j), lanes XOR'd
__device__ __forceinline__ float gumbel_at(int j) {
    unsigned o0, o1;
    threefry01(0u, (unsigned)j, o0, o1);
    unsigned bits = o0 ^ o1;
    float f = __uint_as_float((bits >> 9) | 0x3f800000u) - 1.0f;
    const float TINY = 1.1754943508222875e-38f;
    float u = fmaxf(TINY, f * (1.0f - TINY) + TINY);
    return -logf(-logf(u));
}

// ================= kernels =================

// copy mem_keys->new_keys, mem_vals->new_vals, and key row inv-norms
__global__ __launch_bounds__(128) void k_copy_norm(
    const float* __restrict__ mk, const float* __restrict__ mv,
    float* __restrict__ nk, float* __restrict__ nv) {
    int row = blockIdx.x;
    int t = threadIdx.x;
    const float4* sk = (const float4*)(mk + (size_t)row * KEY_DIM);
    float4* dk = (float4*)(nk + (size_t)row * KEY_DIM);
    const float4* sv = (const float4*)(mv + (size_t)row * H);
    float4* dv = (float4*)(nv + (size_t)row * H);
    float ss = 0.f;
    #pragma unroll
    for (int i = t; i < KEY_DIM/4; i += 128) {
        float4 v = sk[i]; dk[i] = v;
        ss += v.x*v.x + v.y*v.y + v.z*v.z + v.w*v.w;
    }
    #pragma unroll
    for (int i = t; i < H/4; i += 128) dv[i] = sv[i];
    #pragma unroll
    for (int o = 16; o > 0; o >>= 1) ss += __shfl_down_sync(0xffffffffu, ss, o);
    __shared__ float w[4];
    if ((t & 31) == 0) w[t >> 5] = ss;
    __syncthreads();
    if (t == 0) {
        float s = w[0] + w[1] + w[2] + w[3];
        g_kinv[row] = 1.0f / fmaxf(sqrtf(s), EPSN);
    }
}

__global__ __launch_bounds__(128) void k_qnorm(const float* __restrict__ q) {
    int row = blockIdx.x;
    int t = threadIdx.x;
    const float4* sq = (const float4*)(q + (size_t)row * KEY_DIM);
    float ss = 0.f;
    #pragma unroll
    for (int i = t; i < KEY_DIM/4; i += 128) {
        float4 v = sq[i];
        ss += v.x*v.x + v.y*v.y + v.z*v.z + v.w*v.w;
    }
    #pragma unroll
    for (int o = 16; o > 0; o >>= 1) ss += __shfl_down_sync(0xffffffffu, ss, o);
    __shared__ float w[4];
    if ((t & 31) == 0) w[t >> 5] = ss;
    __syncthreads();
    if (t == 0) {
        float s = w[0] + w[1] + w[2] + w[3];
        g_qinv[row] = 1.0f / fmaxf(sqrtf(s), EPSN);
    }
}

// split barcode into bf16 hi/lo
__global__ __launch_bounds__(256) void k_qsplit(const float* __restrict__ q) {
    int idx = blockIdx.x * 256 + threadIdx.x;
    __nv_bfloat16 hi, lo;
    split_bf16(q[idx], hi, lo);
    g_qhi[idx] = hi;
    g_qlo[idx] = lo;
}

// split concat(obs, h) into bf16 hi/lo [256][3072]
__global__ __launch_bounds__(256) void k_asplit(
    const float* __restrict__ obs, const float* __restrict__ hin) {
    int idx = blockIdx.x * 256 + threadIdx.x;  // 256*3072
    int m = idx >> 11;            // careful: 3072 not pow2 -> use div
    m = idx / KTOT;
    int k = idx - m * KTOT;
    float v = (k < DIN) ? obs[(size_t)m*DIN + k] : hin[(size_t)m*H + (k - DIN)];
    __nv_bfloat16 hi, lo;
    split_bf16(v, hi, lo);
    g_ahi[idx] = hi;
    g_alo[idx] = lo;
}

// transpose + split W = concat_k(Wi, Wh) [3072][5120] -> Wt [5120][3072] bf16 hi/lo
__global__ void k_wtrans(const float* __restrict__ Wi, const float* __restrict__ Wh) {
    __shared__ float tile[32][33];
    int k0 = blockIdx.x * 32, n0 = blockIdx.y * 32;
    int tx = threadIdx.x, ty = threadIdx.y;  // (32, 8)
    #pragma unroll
    for (int i = 0; i < 4; i++) {
        int k = k0 + ty + i*8;
        float v = (k < DIN) ? Wi[(size_t)k*FIVE_H + n0 + tx]
                            : Wh[(size_t)(k - DIN)*FIVE_H + n0 + tx];
        tile[ty + i*8][tx] = v;
    }
    __syncthreads();
    #pragma unroll
    for (int i = 0; i < 4; i++) {
        int n = n0 + ty + i*8;
        int k = k0 + tx;
        __nv_bfloat16 hi, lo;
        split_bf16(tile[tx][ty + i*8], hi, lo);
        g_wthi[(size_t)n*KTOT + k] = hi;
        g_wtlo[(size_t)n*KTOT + k] = lo;
    }
}

// ---- HMMA preact: [256 x 5120] = A[256 x 3072] @ Wt^T, CTA 64x128, 8 warps ----
#define PPITCH 40   // bf16 elements per smem row (80 bytes)
__global__ __launch_bounds__(256) void k_preact_mma(
    const float* __restrict__ bi, const float* __restrict__ bh) {
    __shared__ __align__(16) char sm[30720];
    char* smAh = sm;            // 64*80   = 5120
    char* smAl = sm + 5120;
    char* smBh = sm + 10240;    // 128*80  = 10240
    char* smBl = sm + 20480;
    int tid = threadIdx.x;
    int lane = tid & 31, wid = tid >> 5;
    int g = lane >> 2, t2 = (lane & 3) * 2;
    int wm = wid >> 2, wn = wid & 3;          // 2 x 4 warps, tile 32x32
    int n0 = blockIdx.x * 128;
    int m0 = blockIdx.y * 64;

    float acc[2][4][4];
    #pragma unroll
    for (int a = 0; a < 2; a++)
        #pragma unroll
        for (int b = 0; b < 4; b++)
            #pragma unroll
            for (int c = 0; c < 4; c++) acc[a][b][c] = 0.f;

    for (int kc = 0; kc < KTOT; kc += 32) {
        {   // A tile 64x32 (one uint4 per thread)
            int row = tid >> 2, un = tid & 3;
            size_t src = (size_t)(m0 + row)*KTOT + kc + un*8;
            *(uint4*)(smAh + row*80 + un*16) = *(const uint4*)(g_ahi + src);
            *(uint4*)(smAl + row*80 + un*16) = *(const uint4*)(g_alo + src);
        }
        #pragma unroll
        for (int i = 0; i < 2; i++) {  // B tile 128x32
            int u = tid + i*256;
            int row = u >> 2, un = u & 3;
            size_t src = (size_t)(n0 + row)*KTOT + kc + un*8;
            *(uint4*)(smBh + row*80 + un*16) = *(const uint4*)(g_wthi + src);
            *(uint4*)(smBl + row*80 + un*16) = *(const uint4*)(g_wtlo + src);
        }
        __syncthreads();
        #pragma unroll
        for (int ks = 0; ks < 2; ks++) {
            uint32_t ah[2][4], al[2][4];
            #pragma unroll
            for (int mt = 0; mt < 2; mt++) {
                int r_ = wm*32 + mt*16 + g;
                int ko = ks*16 + t2;
                ah[mt][0] = *(const uint32_t*)(smAh + (r_*PPITCH + ko)*2);
                ah[mt][1] = *(const uint32_t*)(smAh + ((r_+8)*PPITCH + ko)*2);
                ah[mt][2] = *(const uint32_t*)(smAh + (r_*PPITCH + ko + 8)*2);
                ah[mt][3] = *(const uint32_t*)(smAh + ((r_+8)*PPITCH + ko + 8)*2);
                al[mt][0] = *(const uint32_t*)(smAl + (r_*PPITCH + ko)*2);
                al[mt][1] = *(const uint32_t*)(smAl + ((r_+8)*PPITCH + ko)*2);
                al[mt][2] = *(const uint32_t*)(smAl + (r_*PPITCH + ko + 8)*2);
                al[mt][3] = *(const uint32_t*)(smAl + ((r_+8)*PPITCH + ko + 8)*2);
            }
            #pragma unroll
            for (int j = 0; j < 4; j++) {
                int c_ = wn*32 + j*8 + g;
                int ko = ks*16 + t2;
                uint32_t bh0 = *(const uint32_t*)(smBh + (c_*PPITCH + ko)*2);
                uint32_t bh1 = *(const uint32_t*)(smBh + (c_*PPITCH + ko + 8)*2);
                uint32_t bl0 = *(const uint32_t*)(smBl + (c_*PPITCH + ko)*2);
                uint32_t bl1 = *(const uint32_t*)(smBl + (c_*PPITCH + ko + 8)*2);
                #pragma unroll
                for (int mt = 0; mt < 2; mt++) {
                    mma_bf16(acc[mt][j], ah[mt], bh0, bh1);
                    mma_bf16(acc[mt][j], ah[mt], bl0, bl1);
                    mma_bf16(acc[mt][j], al[mt], bh0, bh1);
                }
            }
        }
        __syncthreads();
    }
    // epilogue: + bi + bh
    #pragma unroll
    for (int mt = 0; mt < 2; mt++) {
        int m = m0 + wm*32 + mt*16 + g;
        #pragma unroll
        for (int j = 0; j < 4; j++) {
            int n = n0 + wn*32 + j*8 + t2;
            float b0 = bi[n] + bh[n], b1 = bi[n+1] + bh[n+1];
            *(float2*)(g_preact + (size_t)m*FIVE_H + n) =
                make_float2(acc[mt][j][0] + b0, acc[mt][j][1] + b1);
            *(float2*)(g_preact + (size_t)(m+8)*FIVE_H + n) =
                make_float2(acc[mt][j][2] + b0, acc[mt][j][3] + b1);
        }
    }
}

// ---- HMMA sims: CTA 128 keys x 256 queries, 512 thr, fused scaled argmax ----
// dyn smem: sq[256]f (1024) | sbest[256]u64 (2048) | Ah 10240 | Al 10240 | Bh 20480 | Bl 20480
#define SIMS_SMEM 64512
__global__ __launch_bounds__(512, 1) void k_sims_mma(const float* __restrict__ mk) {
    extern __shared__ __align__(16) char dsm[];
    float* sq = (float*)dsm;
    unsigned long long* sbest = (unsigned long long*)(dsm + 1024);
    char* smAh = dsm + 3072;
    char* smAl = dsm + 13312;
    char* smBh = dsm + 23552;
    char* smBl = dsm + 44032;
    int tid = threadIdx.x;
    int lane = tid & 31, wid = tid >> 5;
    int g = lane >> 2, t2 = (lane & 3) * 2;
    int wm = wid >> 2, wn = wid & 3;          // 4 x 4 warps, tile 32x64
    int r0 = blockIdx.x * 128;

    if (tid < 256) { sq[tid] = g_qinv[tid]; sbest[tid] = 0ull; }

    float acc[2][8][4];
    #pragma unroll
    for (int a = 0; a < 2; a++)
        #pragma unroll
        for (int b = 0; b < 8; b++)
            #pragma unroll
            for (int c = 0; c < 4; c++) acc[a][b][c] = 0.f;

    for (int kc = 0; kc < KEY_DIM; kc += 32) {
        #pragma unroll
        for (int i = 0; i < 2; i++) {   // A: 128 rows x 32 k (fp32 -> hi/lo)
            int u = tid + i*512;
            int row = u >> 3, kq = u & 7;
            float4 v = *(const float4*)(mk + (size_t)(r0+row)*KEY_DIM + kc + kq*4);
            __nv_bfloat16 h0,h1,h2,h3,l0,l1,l2,l3;
            split_bf16(v.x, h0, l0); split_bf16(v.y, h1, l1);
            split_bf16(v.z, h2, l2); split_bf16(v.w, h3, l3);
            __nv_bfloat162 ph0(h0, h1), ph1(h2, h3), pl0(l0, l1), pl1(l2, l3);
            uint2 ph = make_uint2(*(unsigned*)&ph0, *(unsigned*)&ph1);
            uint2 pl = make_uint2(*(unsigned*)&pl0, *(unsigned*)&pl1);
            *(uint2*)(smAh + row*80 + kq*8) = ph;
            *(uint2*)(smAl + row*80 + kq*8) = pl;
        }
        #pragma unroll
        for (int i = 0; i < 2; i++) {   // B: 256 rows x 32 k (pre-split)
            int u = tid + i*512;
            int row = u >> 2, un = u & 3;
            size_t src = (size_t)row*KEY_DIM + kc + un*8;
            *(uint4*)(smBh + row*80 + un*16) = *(const uint4*)(g_qhi + src);
            *(uint4*)(smBl + row*80 + un*16) = *(const uint4*)(g_qlo + src);
        }
        __syncthreads();
        #pragma unroll
        for (int ks = 0; ks < 2; ks++) {
            uint32_t ah[2][4], al[2][4];
            #pragma unroll
            for (int mt = 0; mt < 2; mt++) {
                int r_ = wm*32 + mt*16 + g;
                int ko = ks*16 + t2;
                ah[mt][0] = *(const uint32_t*)(smAh + (r_*PPITCH + ko)*2);
                ah[mt][1] = *(const uint32_t*)(smAh + ((r_+8)*PPITCH + ko)*2);
                ah[mt][2] = *(const uint32_t*)(smAh + (r_*PPITCH + ko + 8)*2);
                ah[mt][3] = *(const uint32_t*)(smAh + ((r_+8)*PPITCH + ko + 8)*2);
                al[mt][0] = *(const uint32_t*)(smAl + (r_*PPITCH + ko)*2);
                al[mt][1] = *(const uint32_t*)(smAl + ((r_+8)*PPITCH + ko)*2);
                al[mt][2] = *(const uint32_t*)(smAl + (r_*PPITCH + ko + 8)*2);
                al[mt][3] = *(const uint32_t*)(smAl + ((r_+8)*PPITCH + ko + 8)*2);
            }
            #pragma unroll
            for (int j = 0; j < 8; j++) {
                int c_ = wn*64 + j*8 + g;
                int ko = ks*16 + t2;
                uint32_t bh0 = *(const uint32_t*)(smBh + (c_*PPITCH + ko)*2);
                uint32_t bh1 = *(const uint32_t*)(smBh + (c_*PPITCH + ko + 8)*2);
                uint32_t bl0 = *(const uint32_t*)(smBl + (c_*PPITCH + ko)*2);
                uint32_t bl1 = *(const uint32_t*)(smBl + (c_*PPITCH + ko + 8)*2);
                #pragma unroll
                for (int mt = 0; mt < 2; mt++) {
                    mma_bf16(acc[mt][j], ah[mt], bh0, bh1);
                    mma_bf16(acc[mt][j], ah[mt], bl0, bl1);
                    mma_bf16(acc[mt][j], al[mt], bh0, bh1);
                }
            }
        }
        __syncthreads();
    }

    // epilogue: scale by kinv*qinv, per-column argmax via shared atomicMax
    float kin[2][2];
    #pragma unroll
    for (int mt = 0; mt < 2; mt++) {
        int r_ = r0 + wm*32 + mt*16 + g;
        kin[mt][0] = g_kinv[r_];
        kin[mt][1] = g_kinv[r_ + 8];
    }
    #pragma unroll
    for (int j = 0; j < 8; j++) {
        int c_ = wn*64 + j*8 + t2;
        float q0 = sq[c_], q1 = sq[c_ + 1];
        unsigned long long m0p = 0ull, m1p = 0ull;
        #pragma unroll
        for (int mt = 0; mt < 2; mt++) {
            int r_ = r0 + wm*32 + mt*16 + g;
            unsigned long long p;
            p = pack_vi(acc[mt][j][0] * kin[mt][0] * q0, r_);     if (p > m0p) m0p = p;
            p = pack_vi(acc[mt][j][2] * kin[mt][1] * q0, r_ + 8); if (p > m0p) m0p = p;
            p = pack_vi(acc[mt][j][1] * kin[mt][0] * q1, r_);     if (p > m1p) m1p = p;
            p = pack_vi(acc[mt][j][3] * kin[mt][1] * q1, r_ + 8); if (p > m1p) m1p = p;
        }
        atomicMax(&sbest[c_], m0p);
        atomicMax(&sbest[c_ + 1], m1p);
    }
    __syncthreads();
    if (tid < 256)
        g_ppack[(size_t)blockIdx.x * BB + tid] = sbest[tid];
}

// final argmax across 128 chunks per query
__global__ __launch_bounds__(128) void k_finalmax() {
    int b_ = blockIdx.x;
    int t = threadIdx.x;
    __shared__ unsigned long long s[128];
    s[t] = g_ppack[(size_t)t * BB + b_];
    __syncthreads();
    for (int st = 64; st > 0; st >>= 1) {
        if (t < st) {
            unsigned long long v = s[t + st];
            if (v > s[t]) s[t] = v;
        }
        __syncthreads();
    }
    if (t == 0)
        g_bestidx[b_] = (int)(0x7FFFFFFFu - (unsigned)(s[0] & 0xFFFFFFFFull));
}

// gates + DND readout + h_t/c_t + best_mem_id
__global__ __launch_bounds__(256) void k_lstm(
    const float* __restrict__ c_in, const float* __restrict__ mv,
    float* __restrict__ out) {
    int idx = blockIdx.x * 256 + threadIdx.x;   // 0..262143
    int b_ = idx >> 10, j = idx & 1023;
    int best = g_bestidx[b_];
    const float* p = g_preact + (size_t)b_ * FIVE_H;
    float f  = sigmoidf_(p[j]);
    float it = sigmoidf_(p[H + j]);
    float o  = sigmoidf_(p[2*H + j]);
    float r  = sigmoidf_(p[3*H + j]);
    float cn = tanhf(p[4*H + j]);
    float m  = tanhf(mv[(size_t)best * H + j]);
    float ct = f * c_in[idx] + it * cn + r * m;
    float ht = o * tanhf(ct);
    out[OFF_H + idx] = ht;
    out[OFF_C + idx] = ct;
    if (j == 0) out[OFF_BEST + b_] = (float)best;
}

// generic 64x64 tiled fp32 GEMM: C = act(A[MxK] @ B[KxN] + bias)
template<int RELU>
__global__ __launch_bounds__(256) void k_gemm(
    const float* __restrict__ A, const float* __restrict__ Bm,
    const float* __restrict__ bias, float* __restrict__ C,
    int M, int N, int K) {
    __shared__ float As[16][64];
    __shared__ float Bs[16][64];
    int n0 = blockIdx.x * 64;
    int m0 = blockIdx.y * 64;
    int t = threadIdx.x;
    int tx = t & 15, ty = t >> 4;
    float acc[4][4];
    #pragma unroll
    for (int i = 0; i < 4; i++)
        #pragma unroll
        for (int j = 0; j < 4; j++) acc[i][j] = 0.f;
    for (int k0 = 0; k0 < K; k0 += 16) {
        {
            int row = t >> 2, kq = t & 3;
            float4 v = *(const float4*)(A + (size_t)(m0+row)*K + k0 + kq*4);
            As[kq*4+0][row] = v.x; As[kq*4+1][row] = v.y;
            As[kq*4+2][row] = v.z; As[kq*4+3][row] = v.w;
        }
        {
            int kk = t >> 4, nq = t & 15;
            *(float4*)&Bs[kk][nq*4] =
                *(const float4*)(Bm + (size_t)(k0+kk)*N + n0 + nq*4);
        }
        __syncthreads();
        #pragma unroll
        for (int kk = 0; kk < 16; kk++) {
            float a[4], b[4];
            #pragma unroll
            for (int i = 0; i < 4; i++) a[i] = As[kk][ty + i*16];
            #pragma unroll
            for (int j = 0; j < 4; j++) b[j] = Bs[kk][tx + j*16];
            #pragma unroll
            for (int i = 0; i < 4; i++)
                #pragma unroll
                for (int j = 0; j < 4; j++) acc[i][j] += a[i] * b[j];
        }
        __syncthreads();
    }
    #pragma unroll
    for (int i = 0; i < 4; i++) {
        int m = m0 + ty + i*16;
        #pragma unroll
        for (int j = 0; j < 4; j++) {
            int n = n0 + tx + j*16;
            float v = acc[i][j] + bias[n];
            if (RELU) v = fmaxf(v, 0.f);
            C[(size_t)m*N + n] = v;
        }
    }
}

// per-row: log_softmax stats, entropy, critic value, gumbel-argmax sample
__global__ __launch_bounds__(256) void k_final(
    const float* __restrict__ Wc, const float* __restrict__ bc,
    float* __restrict__ out) {
    int b_ = blockIdx.x;
    int t = threadIdx.x;
    __shared__ float sred[256];
    __shared__ float sgv[256];
    __shared__ int   sgi[256];
    const float* lrow = g_logits + (size_t)b_ * N_ACT;
    float l[4];
    #pragma unroll
    for (int k = 0; k < 4; k++) l[k] = lrow[t + k*256];

    float mx = fmaxf(fmaxf(l[0], l[1]), fmaxf(l[2], l[3]));
    sred[t] = mx; __syncthreads();
    for (int s = 128; s > 0; s >>= 1) {
        if (t < s) sred[t] = fmaxf(sred[t], sred[t+s]);
        __syncthreads();
    }
    mx = sred[0]; __syncthreads();

    float se = 0.f;
    #pragma unroll
    for (int k = 0; k < 4; k++) se += expf(l[k] - mx);
    sred[t] = se; __syncthreads();
    for (int s = 128; s > 0; s >>= 1) {
        if (t < s) sred[t] += sred[t+s];
        __syncthreads();
    }
    float lse = mx + logf(sred[0]); __syncthreads();

    float ent = 0.f;
    #pragma unroll
    for (int k = 0; k < 4; k++) {
        float lp = l[k] - lse;
        ent += expf(lp) * lp;
    }
    sred[t] = ent; __syncthreads();
    for (int s = 128; s > 0; s >>= 1) {
        if (t < s) sred[t] += sred[t+s];
        __syncthreads();
    }
    float entropy = -sred[0]; __syncthreads();

    const float* ha = g_ha + (size_t)b_ * A2C_H;
    float v = ha[t] * Wc[t] + ha[t + 256] * Wc[t + 256];
    sred[t] = v; __syncthreads();
    for (int s = 128; s > 0; s >>= 1) {
        if (t < s) sred[t] += sred[t+s];
        __syncthreads();
    }
    float vt = sred[0] + bc[0];

    float bv = -3.0e38f; int bn = 0;
    #pragma unroll
    for (int k = 0; k < 4; k++) {
        int n = t + k*256;
        float g = gumbel_at(b_ * N_ACT + n);
        float cand = (l[k] - lse) + g;
        if (cand > bv) { bv = cand; bn = n; }
    }
    sgv[t] = bv; sgi[t] = bn; __syncthreads();
    for (int s = 128; s > 0; s >>= 1) {
        if (t < s) {
            if (sgv[t+s] > sgv[t] || (sgv[t+s] == sgv[t] && sgi[t+s] < sgi[t])) {
                sgv[t] = sgv[t+s]; sgi[t] = sgi[t+s];
            }
        }
        __syncthreads();
    }
    if (t == 0) {
        int nbest = sgi[0];
        out[OFF_A + b_] = (float)nbest;
        out[OFF_PROB + b_] = lrow[nbest] - lse;
        out[OFF_V + b_] = vt;
        out[OFF_ENT + b_] = entropy;
    }
}

// last-write-wins scatter of q_t / c_t into the dict copies
__global__ __launch_bounds__(256) void k_scatter(
    const int* __restrict__ widx, const float* __restrict__ q,
    float* __restrict__ out) {
    int b_ = blockIdx.x;
    __shared__ int target;
    if (threadIdx.x == 0) {
        int idx = widx[b_];
        int last = 1;
        for (int b2 = b_ + 1; b2 < BB; b2++)
            if (widx[b2] == idx) { last = 0; break; }
        target = last ? idx : -1;
    }
    __syncthreads();
    int idx = target;
    if (idx < 0) return;
    int t = threadIdx.x;
    const float4* qs = (const float4*)(q + (size_t)b_ * KEY_DIM);
    const float4* cs = (const float4*)(out + OFF_C + (size_t)b_ * H);
    float4* kd = (float4*)(out + OFF_NK + (size_t)idx * KEY_DIM);
    float4* vd = (float4*)(out + OFF_NV + (size_t)idx * H);
    kd[t] = qs[t];
    vd[t] = cs[t];
}

extern "C" void kernel_launch(void* const* d_in, const int* in_sizes, int n_in,
                              void* d_out, int out_size) {
    const float* obs     = (const float*)d_in[0];
    const float* barcode = (const float*)d_in[1];
    const float* h_in    = (const float*)d_in[2];
    const float* c_in    = (const float*)d_in[3];
    const int*   widx    = (const int*)  d_in[4];
    const float* Wi      = (const float*)d_in[5];
    const float* bi      = (const float*)d_in[6];
    const float* Wh      = (const float*)d_in[7];
    const float* bh      = (const float*)d_in[8];
    const float* mk      = (const float*)d_in[9];
    const float* mv      = (const float*)d_in[10];
    const float* Wa      = (const float*)d_in[11];
    const float* ba      = (const float*)d_in[12];
    const float* Wact    = (const float*)d_in[13];
    const float* bact    = (const float*)d_in[14];
    const float* Wc      = (const float*)d_in[15];
    const float* bc      = (const float*)d_in[16];
    float* out = (float*)d_out;

    float* g_ha_ptr; cudaGetSymbolAddress((void**)&g_ha_ptr, g_ha);
    float* g_logits_ptr; cudaGetSymbolAddress((void**)&g_logits_ptr, g_logits);

    cudaFuncSetAttribute(k_sims_mma, cudaFuncAttributeMaxDynamicSharedMemorySize,
                         SIMS_SMEM);

    k_copy_norm<<<DICT_LEN, 128>>>(mk, mv, out + OFF_NK, out + OFF_NV);
    k_qnorm<<<BB, 128>>>(barcode);
    k_qsplit<<<BB*KEY_DIM/256, 256>>>(barcode);
    k_asplit<<<BB*KTOT/256, 256>>>(obs, h_in);
    k_wtrans<<<dim3(KTOT/32, FIVE_H/32), dim3(32, 8)>>>(Wi, Wh);
    k_preact_mma<<<dim3(FIVE_H/128, BB/64), 256>>>(bi, bh);
    k_sims_mma<<<DICT_LEN/128, 512, SIMS_SMEM>>>(mk);
    k_finalmax<<<BB, 128>>>();
    k_lstm<<<BB*H/256, 256>>>(c_in, mv, out);
    k_scatter<<<BB, 256>>>(widx, barcode, out);
    // ha = relu(c_t @ Wa + ba)
    k_gemm<1><<<dim3(A2C_H/64, BB/64), 256>>>(out + OFF_C, Wa, ba, g_ha_ptr,
                                              BB, A2C_H, H);
    // logits = ha @ W_actor + b_actor
    k_gemm<0><<<dim3(N_ACT/64, BB/64), 256>>>(g_ha_ptr, Wact, bact, g_logits_ptr,
                                              BB, N_ACT, A2C_H);
    k_final<<<BB, 256>>>(Wc, bc, out);
}

// round 6
// speedup vs baseline: 2.1804x; 1.0339x over previous
#include <cuda_runtime.h>
#include <cuda_bf16.h>
#include <math.h>
#include <stdint.h>

#define H       1024
#define DIN     2048
#define KEY_DIM 1024
#define DICT_LEN 16384
#define A2C_H   512
#define N_ACT   1024
#define BB      256
#define FIVE_H  (5*H)
#define KTOT    3072
#define EPSN    1e-8f

// ---- output layout (float32, tuple order flattened) ----
#define OFF_A    0
#define OFF_PROB 256
#define OFF_V    512
#define OFF_ENT  768
#define OFF_H    1024
#define OFF_C    (OFF_H + BB*H)
#define OFF_BEST (OFF_C + BB*H)
#define OFF_NK   (OFF_BEST + 256)
#define OFF_NV   (OFF_NK + DICT_LEN*KEY_DIM)

// ---- scratch (static device globals; no allocation allowed) ----
__device__ float g_preact[BB*FIVE_H];
__device__ float g_qinv[BB];
__device__ __nv_bfloat16 g_qhi[BB*KEY_DIM];
__device__ __nv_bfloat16 g_qlo[BB*KEY_DIM];
__device__ __nv_bfloat16 g_ahi[BB*KTOT];
__device__ __nv_bfloat16 g_alo[BB*KTOT];
__device__ __nv_bfloat16 g_wthi[(size_t)FIVE_H*KTOT];
__device__ __nv_bfloat16 g_wtlo[(size_t)FIVE_H*KTOT];
__device__ unsigned long long g_ppack[128 * BB];  // [chunk][query]
__device__ int   g_bestidx[BB];
__device__ float g_ha[BB*A2C_H];
__device__ float g_logits[BB*N_ACT];

__device__ __forceinline__ float sigmoidf_(float x) { return 1.0f / (1.0f + expf(-x)); }

__device__ __forceinline__ unsigned float_flip(float f) {
    unsigned u = __float_as_uint(f);
    return (u & 0x80000000u) ? ~u : (u | 0x80000000u);
}

__device__ __forceinline__ unsigned long long pack_vi(float v, int row) {
    return ((unsigned long long)float_flip(v) << 32) |
           (unsigned)(0x7FFFFFFFu - (unsigned)row);
}

// HMMA m16n8k16 bf16, fp32 accum
__device__ __forceinline__ void mma_bf16(float* c, const uint32_t* a,
                                         uint32_t b0, uint32_t b1) {
    asm volatile(
        "mma.sync.aligned.m16n8k16.row.col.f32.bf16.bf16.f32 "
        "{%0,%1,%2,%3}, {%4,%5,%6,%7}, {%8,%9}, {%0,%1,%2,%3};\n"
        : "+f"(c[0]), "+f"(c[1]), "+f"(c[2]), "+f"(c[3])
        : "r"(a[0]), "r"(a[1]), "r"(a[2]), "r"(a[3]), "r"(b0), "r"(b1));
}

__device__ __forceinline__ void split_bf16(float v, __nv_bfloat16& hi, __nv_bfloat16& lo) {
    hi = __float2bfloat16(v);
    lo = __float2bfloat16(v - __bfloat162float(hi));
}

__device__ __forceinline__ uint32_t smem_u32(const void* p) {
    uint32_t a;
    asm("{ .reg .u64 t; cvta.to.shared.u64 t, %1; cvt.u32.u64 %0, t; }"
        : "=r"(a) : "l"(p));
    return a;
}

__device__ __forceinline__ void cp16(uint32_t s, const void* g) {
    asm volatile("cp.async.cg.shared.global [%0], [%1], 16;" :: "r"(s), "l"(g));
}
#define CP_COMMIT() asm volatile("cp.async.commit_group;" ::: "memory")
#define CP_WAIT1()  asm volatile("cp.async.wait_group 1;" ::: "memory")
#define CP_WAIT0()  asm volatile("cp.async.wait_group 0;" ::: "memory")

// ---- Threefry-2x32-20 with key (0,1)  (jax.random.key(1)) ----
__device__ __forceinline__ void threefry01(unsigned x0, unsigned x1,
                                           unsigned &o0, unsigned &o1) {
    const unsigned ks0 = 0u, ks1 = 1u, ks2 = 0u ^ 1u ^ 0x1BD11BDAu;
    x0 += ks0; x1 += ks1;
#define ROTL(v,r) (((v) << (r)) | ((v) >> (32 - (r))))
#define RND(r) { x0 += x1; x1 = ROTL(x1, r); x1 ^= x0; }
    RND(13) RND(15) RND(26) RND(6)
    x0 += ks1; x1 += ks2 + 1u;
    RND(17) RND(29) RND(16) RND(24)
    x0 += ks2; x1 += ks0 + 2u;
    RND(13) RND(15) RND(26) RND(6)
    x0 += ks0; x1 += ks1 + 3u;
    RND(17) RND(29) RND(16) RND(24)
    x0 += ks1; x1 += ks2 + 4u;
    RND(13) RND(15) RND(26) RND(6)
    x0 += ks2; x1 += ks0 + 5u;
#undef RND
#undef ROTL
    o0 = x0; o1 = x1;
}

// partitionable threefry: counter (0, j), lanes XOR'd
__device__ __forceinline__ float gumbel_at(int j) {
    unsigned o0, o1;
    threefry01(0u, (unsigned)j, o0, o1);
    unsigned bits = o0 ^ o1;
    float f = __uint_as_float((bits >> 9) | 0x3f800000u) - 1.0f;
    const float TINY = 1.1754943508222875e-38f;
    float u = fmaxf(TINY, f * (1.0f - TINY) + TINY);
    return -logf(-logf(u));
}

// ================= kernels =================

// q row inv-norms + bf16 hi/lo split (merged)
__global__ __launch_bounds__(128) void k_qprep(const float* __restrict__ q) {
    int row = blockIdx.x;
    int t = threadIdx.x;
    const float4* sq = (const float4*)(q + (size_t)row * KEY_DIM);
    float ss = 0.f;
    #pragma unroll
    for (int i = t; i < KEY_DIM/4; i += 128) {
        float4 v = sq[i];
        ss += v.x*v.x + v.y*v.y + v.z*v.z + v.w*v.w;
        __nv_bfloat16 h0,h1,h2,h3,l0,l1,l2,l3;
        split_bf16(v.x,h0,l0); split_bf16(v.y,h1,l1);
        split_bf16(v.z,h2,l2); split_bf16(v.w,h3,l3);
        __nv_bfloat162 ph0(h0,h1), ph1(h2,h3), pl0(l0,l1), pl1(l2,l3);
        size_t o = (size_t)row*KEY_DIM + i*4;
        *(__nv_bfloat162*)(g_qhi + o) = ph0;
        *(__nv_bfloat162*)(g_qhi + o + 2) = ph1;
        *(__nv_bfloat162*)(g_qlo + o) = pl0;
        *(__nv_bfloat162*)(g_qlo + o + 2) = pl1;
    }
    #pragma unroll
    for (int o = 16; o > 0; o >>= 1) ss += __shfl_down_sync(0xffffffffu, ss, o);
    __shared__ float w[4];
    if ((t & 31) == 0) w[t >> 5] = ss;
    __syncthreads();
    if (t == 0) {
        float s = w[0] + w[1] + w[2] + w[3];
        g_qinv[row] = 1.0f / fmaxf(sqrtf(s), EPSN);
    }
}

// split concat(obs, h) into bf16 hi/lo [256][3072]
__global__ __launch_bounds__(256) void k_asplit(
    const float* __restrict__ obs, const float* __restrict__ hin) {
    int idx = blockIdx.x * 256 + threadIdx.x;  // 256*3072
    int m = idx / KTOT;
    int k = idx - m * KTOT;
    float v = (k < DIN) ? obs[(size_t)m*DIN + k] : hin[(size_t)m*H + (k - DIN)];
    __nv_bfloat16 hi, lo;
    split_bf16(v, hi, lo);
    g_ahi[idx] = hi;
    g_alo[idx] = lo;
}

// transpose + split W = concat_k(Wi, Wh) [3072][5120] -> Wt [5120][3072] bf16 hi/lo
__global__ void k_wtrans(const float* __restrict__ Wi, const float* __restrict__ Wh) {
    __shared__ float tile[32][33];
    int k0 = blockIdx.x * 32, n0 = blockIdx.y * 32;
    int tx = threadIdx.x, ty = threadIdx.y;  // (32, 8)
    #pragma unroll
    for (int i = 0; i < 4; i++) {
        int k = k0 + ty + i*8;
        float v = (k < DIN) ? Wi[(size_t)k*FIVE_H + n0 + tx]
                            : Wh[(size_t)(k - DIN)*FIVE_H + n0 + tx];
        tile[ty + i*8][tx] = v;
    }
    __syncthreads();
    #pragma unroll
    for (int i = 0; i < 4; i++) {
        int n = n0 + ty + i*8;
        int k = k0 + tx;
        __nv_bfloat16 hi, lo;
        split_bf16(tile[tx][ty + i*8], hi, lo);
        g_wthi[(size_t)n*KTOT + k] = hi;
        g_wtlo[(size_t)n*KTOT + k] = lo;
    }
}

#define PPITCH 40   // bf16 elements per smem row (80 bytes)

// ---- HMMA sims: CTA 128 keys x 256 queries, 512 thr, cp.async 2-stage ----
// dyn smem: sq[256]f @0 | sbest[256]u64 @1024 | skin[128]f @3072 | bufs @3584
#define SIMS_SBUF 61440
#define SIMS_SMEM (3584 + 2*SIMS_SBUF)
__global__ __launch_bounds__(512, 1) void k_sims_mma(const float* __restrict__ mk) {
    extern __shared__ __align__(16) char dsm[];
    float* sq = (float*)dsm;
    unsigned long long* sbest = (unsigned long long*)(dsm + 1024);
    float* skin = (float*)(dsm + 3072);
    uint32_t sb32 = smem_u32(dsm);
    int tid = threadIdx.x;
    int lane = tid & 31, wid = tid >> 5;
    int g = lane >> 2, t2 = (lane & 3) * 2;
    int wm = wid >> 2, wn = wid & 3;          // 4 x 4 warps, tile 32x64
    int r0 = blockIdx.x * 128;

    if (tid < 256) { sq[tid] = g_qinv[tid]; sbest[tid] = 0ull; }

    // per-thread A addressing: i=0/1 -> u = tid + i*512, row = u>>3, kq = u&7
    int arow[2], akq[2];
    #pragma unroll
    for (int i = 0; i < 2; i++) { int u = tid + i*512; arow[i] = u >> 3; akq[i] = u & 7; }

    float acc[2][8][4];
    #pragma unroll
    for (int a = 0; a < 2; a++)
        #pragma unroll
        for (int b = 0; b < 8; b++)
            #pragma unroll
            for (int c = 0; c < 4; c++) acc[a][b][c] = 0.f;

    // B cp.async issue for chunk c into buffer base (byte offset within dsm)
    auto issueB = [&](int c, uint32_t bufo) {
        #pragma unroll
        for (int i = 0; i < 2; i++) {
            int u = tid + i*512;
            int row = u >> 2, un = u & 3;
            uint32_t so = bufo + 20480 + row*80 + un*16;      // Bh
            cp16(sb32 + so, g_qhi + (size_t)row*KEY_DIM + c*32 + un*8);
            cp16(sb32 + so + 20480, g_qlo + (size_t)row*KEY_DIM + c*32 + un*8);
        }
    };

    float4 ra[2];
    float ss[2] = {0.f, 0.f};
    // prologue: chunk 0
    #pragma unroll
    for (int i = 0; i < 2; i++)
        ra[i] = *(const float4*)(mk + (size_t)(r0+arow[i])*KEY_DIM + akq[i]*4);
    issueB(0, 3584);
    CP_COMMIT();

    for (int c = 0; c < 32; c++) {
        int b = c & 1;
        uint32_t bufo = 3584 + b*SIMS_SBUF;
        float4 rn[2];
        if (c + 1 < 32) {
            #pragma unroll
            for (int i = 0; i < 2; i++)
                rn[i] = *(const float4*)(mk + (size_t)(r0+arow[i])*KEY_DIM
                                         + (c+1)*32 + akq[i]*4);
            issueB(c+1, 3584 + (1-b)*SIMS_SBUF);
            CP_COMMIT();
            CP_WAIT1();
        } else {
            CP_WAIT0();
        }
        // convert+store A chunk c, accumulate sumsq
        char* smA = dsm + bufo;
        #pragma unroll
        for (int i = 0; i < 2; i++) {
            float4 v = ra[i];
            ss[i] += v.x*v.x + v.y*v.y + v.z*v.z + v.w*v.w;
            __nv_bfloat16 h0,h1,h2,h3,l0,l1,l2,l3;
            split_bf16(v.x,h0,l0); split_bf16(v.y,h1,l1);
            split_bf16(v.z,h2,l2); split_bf16(v.w,h3,l3);
            __nv_bfloat162 ph0(h0,h1), ph1(h2,h3), pl0(l0,l1), pl1(l2,l3);
            uint2 ph = make_uint2(*(unsigned*)&ph0, *(unsigned*)&ph1);
            uint2 pl = make_uint2(*(unsigned*)&pl0, *(unsigned*)&pl1);
            *(uint2*)(smA + arow[i]*80 + akq[i]*8) = ph;
            *(uint2*)(smA + 10240 + arow[i]*80 + akq[i]*8) = pl;
        }
        __syncthreads();
        char* smAh = smA;
        char* smAl = smA + 10240;
        char* smBh = smA + 20480;
        char* smBl = smA + 40960;
        #pragma unroll
        for (int ks = 0; ks < 2; ks++) {
            uint32_t ah[2][4], al[2][4];
            #pragma unroll
            for (int mt = 0; mt < 2; mt++) {
                int r_ = wm*32 + mt*16 + g;
                int ko = ks*16 + t2;
                ah[mt][0] = *(const uint32_t*)(smAh + (r_*PPITCH + ko)*2);
                ah[mt][1] = *(const uint32_t*)(smAh + ((r_+8)*PPITCH + ko)*2);
                ah[mt][2] = *(const uint32_t*)(smAh + (r_*PPITCH + ko + 8)*2);
                ah[mt][3] = *(const uint32_t*)(smAh + ((r_+8)*PPITCH + ko + 8)*2);
                al[mt][0] = *(const uint32_t*)(smAl + (r_*PPITCH + ko)*2);
                al[mt][1] = *(const uint32_t*)(smAl + ((r_+8)*PPITCH + ko)*2);
                al[mt][2] = *(const uint32_t*)(smAl + (r_*PPITCH + ko + 8)*2);
                al[mt][3] = *(const uint32_t*)(smAl + ((r_+8)*PPITCH + ko + 8)*2);
            }
            #pragma unroll
            for (int j = 0; j < 8; j++) {
                int c_ = wn*64 + j*8 + g;
                int ko = ks*16 + t2;
                uint32_t bh0 = *(const uint32_t*)(smBh + (c_*PPITCH + ko)*2);
                uint32_t bh1 = *(const uint32_t*)(smBh + (c_*PPITCH + ko + 8)*2);
                uint32_t bl0 = *(const uint32_t*)(smBl + (c_*PPITCH + ko)*2);
                uint32_t bl1 = *(const uint32_t*)(smBl + (c_*PPITCH + ko + 8)*2);
                #pragma unroll
                for (int mt = 0; mt < 2; mt++) {
                    mma_bf16(acc[mt][j], ah[mt], bh0, bh1);
                    mma_bf16(acc[mt][j], ah[mt], bl0, bl1);
                    mma_bf16(acc[mt][j], al[mt], bh0, bh1);
                }
            }
        }
        __syncthreads();
        ra[0] = rn[0]; ra[1] = rn[1];
    }

    // finalize kinv for this CTA's 128 rows (8 lanes share a row)
    #pragma unroll
    for (int i = 0; i < 2; i++) {
        float s = ss[i];
        #pragma unroll
        for (int o = 4; o > 0; o >>= 1) s += __shfl_down_sync(0xffffffffu, s, o, 8);
        if ((tid & 7) == 0) skin[arow[i]] = 1.0f / fmaxf(sqrtf(s), EPSN);
    }
    __syncthreads();

    // epilogue: scale by kinv*qinv, per-column argmax via shared atomicMax
    float kin[2][2];
    #pragma unroll
    for (int mt = 0; mt < 2; mt++) {
        int r_ = wm*32 + mt*16 + g;
        kin[mt][0] = skin[r_];
        kin[mt][1] = skin[r_ + 8];
    }
    #pragma unroll
    for (int j = 0; j < 8; j++) {
        int c_ = wn*64 + j*8 + t2;
        float q0 = sq[c_], q1 = sq[c_ + 1];
        unsigned long long m0p = 0ull, m1p = 0ull;
        #pragma unroll
        for (int mt = 0; mt < 2; mt++) {
            int r_ = r0 + wm*32 + mt*16 + g;
            unsigned long long p;
            p = pack_vi(acc[mt][j][0] * kin[mt][0] * q0, r_);     if (p > m0p) m0p = p;
            p = pack_vi(acc[mt][j][2] * kin[mt][1] * q0, r_ + 8); if (p > m0p) m0p = p;
            p = pack_vi(acc[mt][j][1] * kin[mt][0] * q1, r_);     if (p > m1p) m1p = p;
            p = pack_vi(acc[mt][j][3] * kin[mt][1] * q1, r_ + 8); if (p > m1p) m1p = p;
        }
        atomicMax(&sbest[c_], m0p);
        atomicMax(&sbest[c_ + 1], m1p);
    }
    __syncthreads();
    if (tid < 256)
        g_ppack[(size_t)blockIdx.x * BB + tid] = sbest[tid];
}

// ---- HMMA preact: [256 x 5120], CTA 64x128, 8 warps, cp.async 2-stage ----
#define PRE_SBUF 30720
#define PRE_SMEM (2*PRE_SBUF)
__global__ __launch_bounds__(256) void k_preact_mma(
    const float* __restrict__ bi, const float* __restrict__ bh) {
    extern __shared__ __align__(16) char dsm[];
    uint32_t sb32 = smem_u32(dsm);
    int tid = threadIdx.x;
    int lane = tid & 31, wid = tid >> 5;
    int g = lane >> 2, t2 = (lane & 3) * 2;
    int wm = wid >> 2, wn = wid & 3;          // 2 x 4 warps, tile 32x32
    int n0 = blockIdx.x * 128;
    int m0 = blockIdx.y * 64;

    float acc[2][4][4];
    #pragma unroll
    for (int a = 0; a < 2; a++)
        #pragma unroll
        for (int b = 0; b < 4; b++)
            #pragma unroll
            for (int c = 0; c < 4; c++) acc[a][b][c] = 0.f;

    auto issueAB = [&](int kci, uint32_t bufo) {
        {   // A tile 64x32
            int row = tid >> 2, un = tid & 3;
            size_t src = (size_t)(m0 + row)*KTOT + kci*32 + un*8;
            uint32_t so = bufo + row*80 + un*16;
            cp16(sb32 + so, g_ahi + src);
            cp16(sb32 + so + 5120, g_alo + src);
        }
        #pragma unroll
        for (int i = 0; i < 2; i++) {  // B tile 128x32
            int u = tid + i*256;
            int row = u >> 2, un = u & 3;
            size_t src = (size_t)(n0 + row)*KTOT + kci*32 + un*8;
            uint32_t so = bufo + 10240 + row*80 + un*16;
            cp16(sb32 + so, g_wthi + src);
            cp16(sb32 + so + 10240, g_wtlo + src);
        }
    };

    issueAB(0, 0);
    CP_COMMIT();

    for (int kci = 0; kci < 96; kci++) {
        int b = kci & 1;
        if (kci + 1 < 96) {
            issueAB(kci + 1, (uint32_t)((1-b)*PRE_SBUF));
            CP_COMMIT();
            CP_WAIT1();
        } else {
            CP_WAIT0();
        }
        __syncthreads();
        char* smAh = dsm + b*PRE_SBUF;
        char* smAl = smAh + 5120;
        char* smBh = smAh + 10240;
        char* smBl = smAh + 20480;
        #pragma unroll
        for (int ks = 0; ks < 2; ks++) {
            uint32_t ah[2][4], al[2][4];
            #pragma unroll
            for (int mt = 0; mt < 2; mt++) {
                int r_ = wm*32 + mt*16 + g;
                int ko = ks*16 + t2;
                ah[mt][0] = *(const uint32_t*)(smAh + (r_*PPITCH + ko)*2);
                ah[mt][1] = *(const uint32_t*)(smAh + ((r_+8)*PPITCH + ko)*2);
                ah[mt][2] = *(const uint32_t*)(smAh + (r_*PPITCH + ko + 8)*2);
                ah[mt][3] = *(const uint32_t*)(smAh + ((r_+8)*PPITCH + ko + 8)*2);
                al[mt][0] = *(const uint32_t*)(smAl + (r_*PPITCH + ko)*2);
                al[mt][1] = *(const uint32_t*)(smAl + ((r_+8)*PPITCH + ko)*2);
                al[mt][2] = *(const uint32_t*)(smAl + (r_*PPITCH + ko + 8)*2);
                al[mt][3] = *(const uint32_t*)(smAl + ((r_+8)*PPITCH + ko + 8)*2);
            }
            #pragma unroll
            for (int j = 0; j < 4; j++) {
                int c_ = wn*32 + j*8 + g;
                int ko = ks*16 + t2;
                uint32_t bh0 = *(const uint32_t*)(smBh + (c_*PPITCH + ko)*2);
                uint32_t bh1 = *(const uint32_t*)(smBh + (c_*PPITCH + ko + 8)*2);
                uint32_t bl0 = *(const uint32_t*)(smBl + (c_*PPITCH + ko)*2);
                uint32_t bl1 = *(const uint32_t*)(smBl + (c_*PPITCH + ko + 8)*2);
                #pragma unroll
                for (int mt = 0; mt < 2; mt++) {
                    mma_bf16(acc[mt][j], ah[mt], bh0, bh1);
                    mma_bf16(acc[mt][j], ah[mt], bl0, bl1);
                    mma_bf16(acc[mt][j], al[mt], bh0, bh1);
                }
            }
        }
        __syncthreads();
    }
    // epilogue: + bi + bh
    #pragma unroll
    for (int mt = 0; mt < 2; mt++) {
        int m = m0 + wm*32 + mt*16 + g;
        #pragma unroll
        for (int j = 0; j < 4; j++) {
            int n = n0 + wn*32 + j*8 + t2;
            float b0 = bi[n] + bh[n], b1 = bi[n+1] + bh[n+1];
            *(float2*)(g_preact + (size_t)m*FIVE_H + n) =
                make_float2(acc[mt][j][0] + b0, acc[mt][j][1] + b1);
            *(float2*)(g_preact + (size_t)(m+8)*FIVE_H + n) =
                make_float2(acc[mt][j][2] + b0, acc[mt][j][3] + b1);
        }
    }
}

// pure copy: mem_keys->new_keys, mem_vals->new_vals
__global__ __launch_bounds__(128) void k_copy(
    const float* __restrict__ mk, const float* __restrict__ mv,
    float* __restrict__ nk, float* __restrict__ nv) {
    int row = blockIdx.x;
    int t = threadIdx.x;
    const float4* sk = (const float4*)(mk + (size_t)row * KEY_DIM);
    float4* dk = (float4*)(nk + (size_t)row * KEY_DIM);
    const float4* sv = (const float4*)(mv + (size_t)row * H);
    float4* dv = (float4*)(nv + (size_t)row * H);
    #pragma unroll
    for (int i = t; i < KEY_DIM/4; i += 128) dk[i] = sk[i];
    #pragma unroll
    for (int i = t; i < H/4; i += 128) dv[i] = sv[i];
}

// final argmax across 128 chunks per query
__global__ __launch_bounds__(128) void k_finalmax() {
    int b_ = blockIdx.x;
    int t = threadIdx.x;
    __shared__ unsigned long long s[128];
    s[t] = g_ppack[(size_t)t * BB + b_];
    __syncthreads();
    for (int st = 64; st > 0; st >>= 1) {
        if (t < st) {
            unsigned long long v = s[t + st];
            if (v > s[t]) s[t] = v;
        }
        __syncthreads();
    }
    if (t == 0)
        g_bestidx[b_] = (int)(0x7FFFFFFFu - (unsigned)(s[0] & 0xFFFFFFFFull));
}

// gates + DND readout + h_t/c_t + best_mem_id
__global__ __launch_bounds__(256) void k_lstm(
    const float* __restrict__ c_in, const float* __restrict__ mv,
    float* __restrict__ out) {
    int idx = blockIdx.x * 256 + threadIdx.x;   // 0..262143
    int b_ = idx >> 10, j = idx & 1023;
    int best = g_bestidx[b_];
    const float* p = g_preact + (size_t)b_ * FIVE_H;
    float f  = sigmoidf_(p[j]);
    float it = sigmoidf_(p[H + j]);
    float o  = sigmoidf_(p[2*H + j]);
    float r  = sigmoidf_(p[3*H + j]);
    float cn = tanhf(p[4*H + j]);
    float m  = tanhf(mv[(size_t)best * H + j]);
    float ct = f * c_in[idx] + it * cn + r * m;
    float ht = o * tanhf(ct);
    out[OFF_H + idx] = ht;
    out[OFF_C + idx] = ct;
    if (j == 0) out[OFF_BEST + b_] = (float)best;
}

// generic 64x64 tiled fp32 GEMM: C = act(A[MxK] @ B[KxN] + bias)
template<int RELU>
__global__ __launch_bounds__(256) void k_gemm(
    const float* __restrict__ A, const float* __restrict__ Bm,
    const float* __restrict__ bias, float* __restrict__ C,
    int M, int N, int K) {
    __shared__ float As[16][64];
    __shared__ float Bs[16][64];
    int n0 = blockIdx.x * 64;
    int m0 = blockIdx.y * 64;
    int t = threadIdx.x;
    int tx = t & 15, ty = t >> 4;
    float acc[4][4];
    #pragma unroll
    for (int i = 0; i < 4; i++)
        #pragma unroll
        for (int j = 0; j < 4; j++) acc[i][j] = 0.f;
    for (int k0 = 0; k0 < K; k0 += 16) {
        {
            int row = t >> 2, kq = t & 3;
            float4 v = *(const float4*)(A + (size_t)(m0+row)*K + k0 + kq*4);
            As[kq*4+0][row] = v.x; As[kq*4+1][row] = v.y;
            As[kq*4+2][row] = v.z; As[kq*4+3][row] = v.w;
        }
        {
            int kk = t >> 4, nq = t & 15;
            *(float4*)&Bs[kk][nq*4] =
                *(const float4*)(Bm + (size_t)(k0+kk)*N + n0 + nq*4);
        }
        __syncthreads();
        #pragma unroll
        for (int kk = 0; kk < 16; kk++) {
            float a[4], b[4];
            #pragma unroll
            for (int i = 0; i < 4; i++) a[i] = As[kk][ty + i*16];
            #pragma unroll
            for (int j = 0; j < 4; j++) b[j] = Bs[kk][tx + j*16];
            #pragma unroll
            for (int i = 0; i < 4; i++)
                #pragma unroll
                for (int j = 0; j < 4; j++) acc[i][j] += a[i] * b[j];
        }
        __syncthreads();
    }
    #pragma unroll
    for (int i = 0; i < 4; i++) {
        int m = m0 + ty + i*16;
        #pragma unroll
        for (int j = 0; j < 4; j++) {
            int n = n0 + tx + j*16;
            float v = acc[i][j] + bias[n];
            if (RELU) v = fmaxf(v, 0.f);
            C[(size_t)m*N + n] = v;
        }
    }
}

// per-row: log_softmax stats, entropy, critic value, gumbel-argmax sample
__global__ __launch_bounds__(256) void k_final(
    const float* __restrict__ Wc, const float* __restrict__ bc,
    float* __restrict__ out) {
    int b_ = blockIdx.x;
    int t = threadIdx.x;
    __shared__ float sred[256];
    __shared__ float sgv[256];
    __shared__ int   sgi[256];
    const float* lrow = g_logits + (size_t)b_ * N_ACT;
    float l[4];
    #pragma unroll
    for (int k = 0; k < 4; k++) l[k] = lrow[t + k*256];

    float mx = fmaxf(fmaxf(l[0], l[1]), fmaxf(l[2], l[3]));
    sred[t] = mx; __syncthreads();
    for (int s = 128; s > 0; s >>= 1) {
        if (t < s) sred[t] = fmaxf(sred[t], sred[t+s]);
        __syncthreads();
    }
    mx = sred[0]; __syncthreads();

    float se = 0.f;
    #pragma unroll
    for (int k = 0; k < 4; k++) se += expf(l[k] - mx);
    sred[t] = se; __syncthreads();
    for (int s = 128; s > 0; s >>= 1) {
        if (t < s) sred[t] += sred[t+s];
        __syncthreads();
    }
    float lse = mx + logf(sred[0]); __syncthreads();

    float ent = 0.f;
    #pragma unroll
    for (int k = 0; k < 4; k++) {
        float lp = l[k] - lse;
        ent += expf(lp) * lp;
    }
    sred[t] = ent; __syncthreads();
    for (int s = 128; s > 0; s >>= 1) {
        if (t < s) sred[t] += sred[t+s];
        __syncthreads();
    }
    float entropy = -sred[0]; __syncthreads();

    const float* ha = g_ha + (size_t)b_ * A2C_H;
    float v = ha[t] * Wc[t] + ha[t + 256] * Wc[t + 256];
    sred[t] = v; __syncthreads();
    for (int s = 128; s > 0; s >>= 1) {
        if (t < s) sred[t] += sred[t+s];
        __syncthreads();
    }
    float vt = sred[0] + bc[0];

    float bv = -3.0e38f; int bn = 0;
    #pragma unroll
    for (int k = 0; k < 4; k++) {
        int n = t + k*256;
        float g = gumbel_at(b_ * N_ACT + n);
        float cand = (l[k] - lse) + g;
        if (cand > bv) { bv = cand; bn = n; }
    }
    sgv[t] = bv; sgi[t] = bn; __syncthreads();
    for (int s = 128; s > 0; s >>= 1) {
        if (t < s) {
            if (sgv[t+s] > sgv[t] || (sgv[t+s] == sgv[t] && sgi[t+s] < sgi[t])) {
                sgv[t] = sgv[t+s]; sgi[t] = sgi[t+s];
            }
        }
        __syncthreads();
    }
    if (t == 0) {
        int nbest = sgi[0];
        out[OFF_A + b_] = (float)nbest;
        out[OFF_PROB + b_] = lrow[nbest] - lse;
        out[OFF_V + b_] = vt;
        out[OFF_ENT + b_] = entropy;
    }
}

// last-write-wins scatter of q_t / c_t into the dict copies
__global__ __launch_bounds__(256) void k_scatter(
    const int* __restrict__ widx, const float* __restrict__ q,
    float* __restrict__ out) {
    int b_ = blockIdx.x;
    __shared__ int target;
    if (threadIdx.x == 0) {
        int idx = widx[b_];
        int last = 1;
        for (int b2 = b_ + 1; b2 < BB; b2++)
            if (widx[b2] == idx) { last = 0; break; }
        target = last ? idx : -1;
    }
    __syncthreads();
    int idx = target;
    if (idx < 0) return;
    int t = threadIdx.x;
    const float4* qs = (const float4*)(q + (size_t)b_ * KEY_DIM);
    const float4* cs = (const float4*)(out + OFF_C + (size_t)b_ * H);
    float4* kd = (float4*)(out + OFF_NK + (size_t)idx * KEY_DIM);
    float4* vd = (float4*)(out + OFF_NV + (size_t)idx * H);
    kd[t] = qs[t];
    vd[t] = cs[t];
}

extern "C" void kernel_launch(void* const* d_in, const int* in_sizes, int n_in,
                              void* d_out, int out_size) {
    const float* obs     = (const float*)d_in[0];
    const float* barcode = (const float*)d_in[1];
    const float* h_in    = (const float*)d_in[2];
    const float* c_in    = (const float*)d_in[3];
    const int*   widx    = (const int*)  d_in[4];
    const float* Wi      = (const float*)d_in[5];
    const float* bi      = (const float*)d_in[6];
    const float* Wh      = (const float*)d_in[7];
    const float* bh      = (const float*)d_in[8];
    const float* mk      = (const float*)d_in[9];
    const float* mv      = (const float*)d_in[10];
    const float* Wa      = (const float*)d_in[11];
    const float* ba      = (const float*)d_in[12];
    const float* Wact    = (const float*)d_in[13];
    const float* bact    = (const float*)d_in[14];
    const float* Wc      = (const float*)d_in[15];
    const float* bc      = (const float*)d_in[16];
    float* out = (float*)d_out;

    float* g_ha_ptr; cudaGetSymbolAddress((void**)&g_ha_ptr, g_ha);
    float* g_logits_ptr; cudaGetSymbolAddress((void**)&g_logits_ptr, g_logits);

    cudaFuncSetAttribute(k_sims_mma, cudaFuncAttributeMaxDynamicSharedMemorySize,
                         SIMS_SMEM);
    cudaFuncSetAttribute(k_preact_mma, cudaFuncAttributeMaxDynamicSharedMemorySize,
                         PRE_SMEM);

    k_qprep<<<BB, 128>>>(barcode);
    k_asplit<<<BB*KTOT/256, 256>>>(obs, h_in);
    k_wtrans<<<dim3(KTOT/32, FIVE_H/32), dim3(32, 8)>>>(Wi, Wh);
    k_sims_mma<<<DICT_LEN/128, 512, SIMS_SMEM>>>(mk);       // launch #4 -> profiled
    k_preact_mma<<<dim3(FIVE_H/128, BB/64), 256, PRE_SMEM>>>(bi, bh);
    k_copy<<<DICT_LEN, 128>>>(mk, mv, out + OFF_NK, out + OFF_NV);
    k_finalmax<<<BB, 128>>>();
    k_lstm<<<BB*H/256, 256>>>(c_in, mv, out);
    k_scatter<<<BB, 256>>>(widx, barcode, out);
    // ha = relu(c_t @ Wa + ba)
    k_gemm<1><<<dim3(A2C_H/64, BB/64), 256>>>(out + OFF_C, Wa, ba, g_ha_ptr,
                                              BB, A2C_H, H);
    // logits = ha @ W_actor + b_actor
    k_gemm<0><<<dim3(N_ACT/64, BB/64), 256>>>(g_ha_ptr, Wact, bact, g_logits_ptr,
                                              BB, N_ACT, A2C_H);
    k_final<<<BB, 256>>>(Wc, bc, out);
}

// round 7
// speedup vs baseline: 2.3340x; 1.0704x over previous
#include <cuda_runtime.h>
#include <cuda_bf16.h>
#include <math.h>
#include <stdint.h>

#define H       1024
#define DIN     2048
#define KEY_DIM 1024
#define DICT_LEN 16384
#define A2C_H   512
#define N_ACT   1024
#define BB      256
#define FIVE_H  (5*H)
#define KTOT    3072
#define EPSN    1e-8f

// ---- output layout (float32, tuple order flattened) ----
#define OFF_A    0
#define OFF_PROB 256
#define OFF_V    512
#define OFF_ENT  768
#define OFF_H    1024
#define OFF_C    (OFF_H + BB*H)
#define OFF_BEST (OFF_C + BB*H)
#define OFF_NK   (OFF_BEST + 256)
#define OFF_NV   (OFF_NK + DICT_LEN*KEY_DIM)

// ---- scratch (static device globals; no allocation allowed) ----
__device__ float g_preact[BB*FIVE_H];
__device__ float g_qinv[BB];
__device__ __nv_bfloat16 g_qhi[BB*KEY_DIM];
__device__ __nv_bfloat16 g_qlo[BB*KEY_DIM];
__device__ __nv_bfloat16 g_ahi[BB*KTOT];
__device__ __nv_bfloat16 g_alo[BB*KTOT];
__device__ __nv_bfloat16 g_wthi[(size_t)FIVE_H*KTOT];
__device__ __nv_bfloat16 g_wtlo[(size_t)FIVE_H*KTOT];
__device__ unsigned long long g_ppack[128 * BB];  // [chunk][query]
__device__ int   g_bestidx[BB];
__device__ float g_ha[BB*A2C_H];
__device__ float g_logits[BB*N_ACT];

__device__ __forceinline__ float sigmoidf_(float x) { return 1.0f / (1.0f + expf(-x)); }

__device__ __forceinline__ unsigned float_flip(float f) {
    unsigned u = __float_as_uint(f);
    return (u & 0x80000000u) ? ~u : (u | 0x80000000u);
}

__device__ __forceinline__ unsigned long long pack_vi(float v, int row) {
    return ((unsigned long long)float_flip(v) << 32) |
           (unsigned)(0x7FFFFFFFu - (unsigned)row);
}

// HMMA m16n8k16 bf16, fp32 accum
__device__ __forceinline__ void mma_bf16(float* c, const uint32_t* a,
                                         uint32_t b0, uint32_t b1) {
    asm volatile(
        "mma.sync.aligned.m16n8k16.row.col.f32.bf16.bf16.f32 "
        "{%0,%1,%2,%3}, {%4,%5,%6,%7}, {%8,%9}, {%0,%1,%2,%3};\n"
        : "+f"(c[0]), "+f"(c[1]), "+f"(c[2]), "+f"(c[3])
        : "r"(a[0]), "r"(a[1]), "r"(a[2]), "r"(a[3]), "r"(b0), "r"(b1));
}

__device__ __forceinline__ void split_bf16(float v, __nv_bfloat16& hi, __nv_bfloat16& lo) {
    hi = __float2bfloat16(v);
    lo = __float2bfloat16(v - __bfloat162float(hi));
}

__device__ __forceinline__ uint32_t smem_u32(const void* p) {
    uint32_t a;
    asm("{ .reg .u64 t; cvta.to.shared.u64 t, %1; cvt.u32.u64 %0, t; }"
        : "=r"(a) : "l"(p));
    return a;
}

__device__ __forceinline__ void cp16(uint32_t s, const void* g) {
    asm volatile("cp.async.cg.shared.global [%0], [%1], 16;" :: "r"(s), "l"(g));
}
#define CP_COMMIT() asm volatile("cp.async.commit_group;" ::: "memory")
#define CP_WAIT0()  asm volatile("cp.async.wait_group 0;" ::: "memory")

// ---- Threefry-2x32-20 with key (0,1)  (jax.random.key(1)) ----
__device__ __forceinline__ void threefry01(unsigned x0, unsigned x1,
                                           unsigned &o0, unsigned &o1) {
    const unsigned ks0 = 0u, ks1 = 1u, ks2 = 0u ^ 1u ^ 0x1BD11BDAu;
    x0 += ks0; x1 += ks1;
#define ROTL(v,r) (((v) << (r)) | ((v) >> (32 - (r))))
#define RND(r) { x0 += x1; x1 = ROTL(x1, r); x1 ^= x0; }
    RND(13) RND(15) RND(26) RND(6)
    x0 += ks1; x1 += ks2 + 1u;
    RND(17) RND(29) RND(16) RND(24)
    x0 += ks2; x1 += ks0 + 2u;
    RND(13) RND(15) RND(26) RND(6)
    x0 += ks0; x1 += ks1 + 3u;
    RND(17) RND(29) RND(16) RND(24)
    x0 += ks1; x1 += ks2 + 4u;
    RND(13) RND(15) RND(26) RND(6)
    x0 += ks2; x1 += ks0 + 5u;
#undef RND
#undef ROTL
    o0 = x0; o1 = x1;
}

// partitionable threefry: counter (0, j), lanes XOR'd
__device__ __forceinline__ float gumbel_at(int j) {
    unsigned o0, o1;
    threefry01(0u, (unsigned)j, o0, o1);
    unsigned bits = o0 ^ o1;
    float f = __uint_as_float((bits >> 9) | 0x3f800000u) - 1.0f;
    const float TINY = 1.1754943508222875e-38f;
    float u = fmaxf(TINY, f * (1.0f - TINY) + TINY);
    return -logf(-logf(u));
}

// ================= kernels =================

// q row inv-norms + bf16 hi/lo split (merged)
__global__ __launch_bounds__(128) void k_qprep(const float* __restrict__ q) {
    int row = blockIdx.x;
    int t = threadIdx.x;
    const float4* sq = (const float4*)(q + (size_t)row * KEY_DIM);
    float ss = 0.f;
    #pragma unroll
    for (int i = t; i < KEY_DIM/4; i += 128) {
        float4 v = sq[i];
        ss += v.x*v.x + v.y*v.y + v.z*v.z + v.w*v.w;
        __nv_bfloat16 h0,h1,h2,h3,l0,l1,l2,l3;
        split_bf16(v.x,h0,l0); split_bf16(v.y,h1,l1);
        split_bf16(v.z,h2,l2); split_bf16(v.w,h3,l3);
        __nv_bfloat162 ph0(h0,h1), ph1(h2,h3), pl0(l0,l1), pl1(l2,l3);
        size_t o = (size_t)row*KEY_DIM + i*4;
        *(__nv_bfloat162*)(g_qhi + o) = ph0;
        *(__nv_bfloat162*)(g_qhi + o + 2) = ph1;
        *(__nv_bfloat162*)(g_qlo + o) = pl0;
        *(__nv_bfloat162*)(g_qlo + o + 2) = pl1;
    }
    #pragma unroll
    for (int o = 16; o > 0; o >>= 1) ss += __shfl_down_sync(0xffffffffu, ss, o);
    __shared__ float w[4];
    if ((t & 31) == 0) w[t >> 5] = ss;
    __syncthreads();
    if (t == 0) {
        float s = w[0] + w[1] + w[2] + w[3];
        g_qinv[row] = 1.0f / fmaxf(sqrtf(s), EPSN);
    }
}

// split concat(obs, h) into bf16 hi/lo [256][3072]
__global__ __launch_bounds__(256) void k_asplit(
    const float* __restrict__ obs, const float* __restrict__ hin) {
    int idx = blockIdx.x * 256 + threadIdx.x;  // 256*3072
    int m = idx / KTOT;
    int k = idx - m * KTOT;
    float v = (k < DIN) ? obs[(size_t)m*DIN + k] : hin[(size_t)m*H + (k - DIN)];
    __nv_bfloat16 hi, lo;
    split_bf16(v, hi, lo);
    g_ahi[idx] = hi;
    g_alo[idx] = lo;
}

// transpose + split W = concat_k(Wi, Wh) [3072][5120] -> Wt [5120][3072] bf16 hi/lo
__global__ void k_wtrans(const float* __restrict__ Wi, const float* __restrict__ Wh) {
    __shared__ float tile[32][33];
    int k0 = blockIdx.x * 32, n0 = blockIdx.y * 32;
    int tx = threadIdx.x, ty = threadIdx.y;  // (32, 8)
    #pragma unroll
    for (int i = 0; i < 4; i++) {
        int k = k0 + ty + i*8;
        float v = (k < DIN) ? Wi[(size_t)k*FIVE_H + n0 + tx]
                            : Wh[(size_t)(k - DIN)*FIVE_H + n0 + tx];
        tile[ty + i*8][tx] = v;
    }
    __syncthreads();
    #pragma unroll
    for (int i = 0; i < 4; i++) {
        int n = n0 + ty + i*8;
        int k = k0 + tx;
        __nv_bfloat16 hi, lo;
        split_bf16(tile[tx][ty + i*8], hi, lo);
        g_wthi[(size_t)n*KTOT + k] = hi;
        g_wtlo[(size_t)n*KTOT + k] = lo;
    }
}

#define PPITCH 40   // bf16 elements per smem row (80 bytes)

// ---- HMMA sims: CTA 128 keys x 256 queries, 512 thr, 1 sync/chunk ----
// dyn smem: sq[256]f @0 | sbest[256]u64 @1024 | skin[128]f @3072 | bufs @3584
#define SIMS_SBUF 61440
#define SIMS_SMEM (3584 + 2*SIMS_SBUF)
__global__ __launch_bounds__(512, 1) void k_sims_mma(const float* __restrict__ mk) {
    extern __shared__ __align__(16) char dsm[];
    float* sq = (float*)dsm;
    unsigned long long* sbest = (unsigned long long*)(dsm + 1024);
    float* skin = (float*)(dsm + 3072);
    uint32_t sb32 = smem_u32(dsm);
    int tid = threadIdx.x;
    int lane = tid & 31, wid = tid >> 5;
    int g = lane >> 2, t2 = (lane & 3) * 2;
    int wm = wid >> 2, wn = wid & 3;          // 4 x 4 warps, tile 32x64
    int r0 = blockIdx.x * 128;

    if (tid < 256) { sq[tid] = g_qinv[tid]; sbest[tid] = 0ull; }

    int arow[2], akq[2];
    #pragma unroll
    for (int i = 0; i < 2; i++) { int u = tid + i*512; arow[i] = u >> 3; akq[i] = u & 7; }

    float acc[2][8][4];
    #pragma unroll
    for (int a = 0; a < 2; a++)
        #pragma unroll
        for (int b = 0; b < 8; b++)
            #pragma unroll
            for (int c = 0; c < 4; c++) acc[a][b][c] = 0.f;

    auto issueB = [&](int c, uint32_t bufo) {
        #pragma unroll
        for (int i = 0; i < 2; i++) {
            int u = tid + i*512;
            int row = u >> 2, un = u & 3;
            uint32_t so = bufo + 20480 + row*80 + un*16;      // Bh
            cp16(sb32 + so, g_qhi + (size_t)row*KEY_DIM + c*32 + un*8);
            cp16(sb32 + so + 20480, g_qlo + (size_t)row*KEY_DIM + c*32 + un*8);
        }
    };

    float4 ra[2];
    float ss[2] = {0.f, 0.f};
    #pragma unroll
    for (int i = 0; i < 2; i++)
        ra[i] = *(const float4*)(mk + (size_t)(r0+arow[i])*KEY_DIM + akq[i]*4);
    issueB(0, 3584);
    CP_COMMIT();

    for (int c = 0; c < 32; c++) {
        int b = c & 1;
        uint32_t bufo = 3584 + b*SIMS_SBUF;
        char* smA = dsm + bufo;
        float4 rn[2];
        if (c + 1 < 32) {
            #pragma unroll
            for (int i = 0; i < 2; i++)
                rn[i] = *(const float4*)(mk + (size_t)(r0+arow[i])*KEY_DIM
                                         + (c+1)*32 + akq[i]*4);
        }
        // convert+store A chunk c into buffer b (safe: c-2's MMA on b finished
        // before all warps passed the single sync at iteration c-1)
        #pragma unroll
        for (int i = 0; i < 2; i++) {
            float4 v = ra[i];
            ss[i] += v.x*v.x + v.y*v.y + v.z*v.z + v.w*v.w;
            __nv_bfloat16 h0,h1,h2,h3,l0,l1,l2,l3;
            split_bf16(v.x,h0,l0); split_bf16(v.y,h1,l1);
            split_bf16(v.z,h2,l2); split_bf16(v.w,h3,l3);
            __nv_bfloat162 ph0(h0,h1), ph1(h2,h3), pl0(l0,l1), pl1(l2,l3);
            uint2 ph = make_uint2(*(unsigned*)&ph0, *(unsigned*)&ph1);
            uint2 pl = make_uint2(*(unsigned*)&pl0, *(unsigned*)&pl1);
            *(uint2*)(smA + arow[i]*80 + akq[i]*8) = ph;
            *(uint2*)(smA + 10240 + arow[i]*80 + akq[i]*8) = pl;
        }
        CP_WAIT0();            // B(c) landed (only group outstanding)
        __syncthreads();       // A(c) + B(c) visible to all; c-1 MMA complete
        if (c + 1 < 32) {
            issueB(c+1, 3584 + (1-b)*SIMS_SBUF);   // safe after sync
            CP_COMMIT();
        }
        char* smAh = smA;
        char* smAl = smA + 10240;
        char* smBh = smA + 20480;
        char* smBl = smA + 40960;
        #pragma unroll
        for (int ks = 0; ks < 2; ks++) {
            uint32_t ah[2][4], al[2][4];
            #pragma unroll
            for (int mt = 0; mt < 2; mt++) {
                int r_ = wm*32 + mt*16 + g;
                int ko = ks*16 + t2;
                ah[mt][0] = *(const uint32_t*)(smAh + (r_*PPITCH + ko)*2);
                ah[mt][1] = *(const uint32_t*)(smAh + ((r_+8)*PPITCH + ko)*2);
                ah[mt][2] = *(const uint32_t*)(smAh + (r_*PPITCH + ko + 8)*2);
                ah[mt][3] = *(const uint32_t*)(smAh + ((r_+8)*PPITCH + ko + 8)*2);
                al[mt][0] = *(const uint32_t*)(smAl + (r_*PPITCH + ko)*2);
                al[mt][1] = *(const uint32_t*)(smAl + ((r_+8)*PPITCH + ko)*2);
                al[mt][2] = *(const uint32_t*)(smAl + (r_*PPITCH + ko + 8)*2);
                al[mt][3] = *(const uint32_t*)(smAl + ((r_+8)*PPITCH + ko + 8)*2);
            }
            #pragma unroll
            for (int j = 0; j < 8; j++) {
                int c_ = wn*64 + j*8 + g;
                int ko = ks*16 + t2;
                uint32_t bh0 = *(const uint32_t*)(smBh + (c_*PPITCH + ko)*2);
                uint32_t bh1 = *(const uint32_t*)(smBh + (c_*PPITCH + ko + 8)*2);
                uint32_t bl0 = *(const uint32_t*)(smBl + (c_*PPITCH + ko)*2);
                uint32_t bl1 = *(const uint32_t*)(smBl + (c_*PPITCH + ko + 8)*2);
                #pragma unroll
                for (int mt = 0; mt < 2; mt++) {
                    mma_bf16(acc[mt][j], ah[mt], bh0, bh1);
                    mma_bf16(acc[mt][j], ah[mt], bl0, bl1);
                    mma_bf16(acc[mt][j], al[mt], bh0, bh1);
                }
            }
        }
        if (c + 1 < 32) { ra[0] = rn[0]; ra[1] = rn[1]; }
    }

    // finalize kinv for this CTA's 128 rows (8 lanes share a row)
    #pragma unroll
    for (int i = 0; i < 2; i++) {
        float s = ss[i];
        #pragma unroll
        for (int o = 4; o > 0; o >>= 1) s += __shfl_down_sync(0xffffffffu, s, o, 8);
        if ((tid & 7) == 0) skin[arow[i]] = 1.0f / fmaxf(sqrtf(s), EPSN);
    }
    __syncthreads();

    // epilogue: scale by kinv*qinv, per-column argmax via shared atomicMax
    float kin[2][2];
    #pragma unroll
    for (int mt = 0; mt < 2; mt++) {
        int r_ = wm*32 + mt*16 + g;
        kin[mt][0] = skin[r_];
        kin[mt][1] = skin[r_ + 8];
    }
    #pragma unroll
    for (int j = 0; j < 8; j++) {
        int c_ = wn*64 + j*8 + t2;
        float q0 = sq[c_], q1 = sq[c_ + 1];
        unsigned long long m0p = 0ull, m1p = 0ull;
        #pragma unroll
        for (int mt = 0; mt < 2; mt++) {
            int r_ = r0 + wm*32 + mt*16 + g;
            unsigned long long p;
            p = pack_vi(acc[mt][j][0] * kin[mt][0] * q0, r_);     if (p > m0p) m0p = p;
            p = pack_vi(acc[mt][j][2] * kin[mt][1] * q0, r_ + 8); if (p > m0p) m0p = p;
            p = pack_vi(acc[mt][j][1] * kin[mt][0] * q1, r_);     if (p > m1p) m1p = p;
            p = pack_vi(acc[mt][j][3] * kin[mt][1] * q1, r_ + 8); if (p > m1p) m1p = p;
        }
        atomicMax(&sbest[c_], m0p);
        atomicMax(&sbest[c_ + 1], m1p);
    }
    __syncthreads();
    if (tid < 256)
        g_ppack[(size_t)blockIdx.x * BB + tid] = sbest[tid];
}

// ---- HMMA preact: [256 x 5120], CTA 64x128, 8 warps, 1 sync/chunk ----
#define PRE_SBUF 30720
#define PRE_SMEM (2*PRE_SBUF)
__global__ __launch_bounds__(256) void k_preact_mma(
    const float* __restrict__ bi, const float* __restrict__ bh) {
    extern __shared__ __align__(16) char dsm[];
    uint32_t sb32 = smem_u32(dsm);
    int tid = threadIdx.x;
    int lane = tid & 31, wid = tid >> 5;
    int g = lane >> 2, t2 = (lane & 3) * 2;
    int wm = wid >> 2, wn = wid & 3;          // 2 x 4 warps, tile 32x32
    int n0 = blockIdx.x * 128;
    int m0 = blockIdx.y * 64;

    float acc[2][4][4];
    #pragma unroll
    for (int a = 0; a < 2; a++)
        #pragma unroll
        for (int b = 0; b < 4; b++)
            #pragma unroll
            for (int c = 0; c < 4; c++) acc[a][b][c] = 0.f;

    auto issueAB = [&](int kci, uint32_t bufo) {
        {   // A tile 64x32
            int row = tid >> 2, un = tid & 3;
            size_t src = (size_t)(m0 + row)*KTOT + kci*32 + un*8;
            uint32_t so = bufo + row*80 + un*16;
            cp16(sb32 + so, g_ahi + src);
            cp16(sb32 + so + 5120, g_alo + src);
        }
        #pragma unroll
        for (int i = 0; i < 2; i++) {  // B tile 128x32
            int u = tid + i*256;
            int row = u >> 2, un = u & 3;
            size_t src = (size_t)(n0 + row)*KTOT + kci*32 + un*8;
            uint32_t so = bufo + 10240 + row*80 + un*16;
            cp16(sb32 + so, g_wthi + src);
            cp16(sb32 + so + 10240, g_wtlo + src);
        }
    };

    issueAB(0, 0);
    CP_COMMIT();

    for (int kci = 0; kci < 96; kci++) {
        int b = kci & 1;
        CP_WAIT0();            // chunk kci landed
        __syncthreads();       // all warps done with kci-1 MMA; data visible
        if (kci + 1 < 96) {
            issueAB(kci + 1, (uint32_t)((1-b)*PRE_SBUF));  // safe after sync
            CP_COMMIT();
        }
        char* smAh = dsm + b*PRE_SBUF;
        char* smAl = smAh + 5120;
        char* smBh = smAh + 10240;
        char* smBl = smAh + 20480;
        #pragma unroll
        for (int ks = 0; ks < 2; ks++) {
            uint32_t ah[2][4], al[2][4];
            #pragma unroll
            for (int mt = 0; mt < 2; mt++) {
                int r_ = wm*32 + mt*16 + g;
                int ko = ks*16 + t2;
                ah[mt][0] = *(const uint32_t*)(smAh + (r_*PPITCH + ko)*2);
                ah[mt][1] = *(const uint32_t*)(smAh + ((r_+8)*PPITCH + ko)*2);
                ah[mt][2] = *(const uint32_t*)(smAh + (r_*PPITCH + ko + 8)*2);
                ah[mt][3] = *(const uint32_t*)(smAh + ((r_+8)*PPITCH + ko + 8)*2);
                al[mt][0] = *(const uint32_t*)(smAl + (r_*PPITCH + ko)*2);
                al[mt][1] = *(const uint32_t*)(smAl + ((r_+8)*PPITCH + ko)*2);
                al[mt][2] = *(const uint32_t*)(smAl + (r_*PPITCH + ko + 8)*2);
                al[mt][3] = *(const uint32_t*)(smAl + ((r_+8)*PPITCH + ko + 8)*2);
            }
            #pragma unroll
            for (int j = 0; j < 4; j++) {
                int c_ = wn*32 + j*8 + g;
                int ko = ks*16 + t2;
                uint32_t bh0 = *(const uint32_t*)(smBh + (c_*PPITCH + ko)*2);
                uint32_t bh1 = *(const uint32_t*)(smBh + (c_*PPITCH + ko + 8)*2);
                uint32_t bl0 = *(const uint32_t*)(smBl + (c_*PPITCH + ko)*2);
                uint32_t bl1 = *(const uint32_t*)(smBl + (c_*PPITCH + ko + 8)*2);
                #pragma unroll
                for (int mt = 0; mt < 2; mt++) {
                    mma_bf16(acc[mt][j], ah[mt], bh0, bh1);
                    mma_bf16(acc[mt][j], ah[mt], bl0, bl1);
                    mma_bf16(acc[mt][j], al[mt], bh0, bh1);
                }
            }
        }
    }
    // epilogue: + bi + bh
    #pragma unroll
    for (int mt = 0; mt < 2; mt++) {
        int m = m0 + wm*32 + mt*16 + g;
        #pragma unroll
        for (int j = 0; j < 4; j++) {
            int n = n0 + wn*32 + j*8 + t2;
            float b0 = bi[n] + bh[n], b1 = bi[n+1] + bh[n+1];
            *(float2*)(g_preact + (size_t)m*FIVE_H + n) =
                make_float2(acc[mt][j][0] + b0, acc[mt][j][1] + b1);
            *(float2*)(g_preact + (size_t)(m+8)*FIVE_H + n) =
                make_float2(acc[mt][j][2] + b0, acc[mt][j][3] + b1);
        }
    }
}

// pure copy: mem_keys->new_keys, mem_vals->new_vals
__global__ __launch_bounds__(128) void k_copy(
    const float* __restrict__ mk, const float* __restrict__ mv,
    float* __restrict__ nk, float* __restrict__ nv) {
    int row = blockIdx.x;
    int t = threadIdx.x;
    const float4* sk = (const float4*)(mk + (size_t)row * KEY_DIM);
    float4* dk = (float4*)(nk + (size_t)row * KEY_DIM);
    const float4* sv = (const float4*)(mv + (size_t)row * H);
    float4* dv = (float4*)(nv + (size_t)row * H);
    #pragma unroll
    for (int i = t; i < KEY_DIM/4; i += 128) dk[i] = sk[i];
    #pragma unroll
    for (int i = t; i < H/4; i += 128) dv[i] = sv[i];
}

// final argmax across 128 chunks per query
__global__ __launch_bounds__(128) void k_finalmax() {
    int b_ = blockIdx.x;
    int t = threadIdx.x;
    __shared__ unsigned long long s[128];
    s[t] = g_ppack[(size_t)t * BB + b_];
    __syncthreads();
    for (int st = 64; st > 0; st >>= 1) {
        if (t < st) {
            unsigned long long v = s[t + st];
            if (v > s[t]) s[t] = v;
        }
        __syncthreads();
    }
    if (t == 0)
        g_bestidx[b_] = (int)(0x7FFFFFFFu - (unsigned)(s[0] & 0xFFFFFFFFull));
}

// gates + DND readout + h_t/c_t + best_mem_id
__global__ __launch_bounds__(256) void k_lstm(
    const float* __restrict__ c_in, const float* __restrict__ mv,
    float* __restrict__ out) {
    int idx = blockIdx.x * 256 + threadIdx.x;   // 0..262143
    int b_ = idx >> 10, j = idx & 1023;
    int best = g_bestidx[b_];
    const float* p = g_preact + (size_t)b_ * FIVE_H;
    float f  = sigmoidf_(p[j]);
    float it = sigmoidf_(p[H + j]);
    float o  = sigmoidf_(p[2*H + j]);
    float r  = sigmoidf_(p[3*H + j]);
    float cn = tanhf(p[4*H + j]);
    float m  = tanhf(mv[(size_t)best * H + j]);
    float ct = f * c_in[idx] + it * cn + r * m;
    float ht = o * tanhf(ct);
    out[OFF_H + idx] = ht;
    out[OFF_C + idx] = ct;
    if (j == 0) out[OFF_BEST + b_] = (float)best;
}

// generic 64x64 tiled fp32 GEMM: C = act(A[MxK] @ B[KxN] + bias)
template<int RELU>
__global__ __launch_bounds__(256) void k_gemm(
    const float* __restrict__ A, const float* __restrict__ Bm,
    const float* __restrict__ bias, float* __restrict__ C,
    int M, int N, int K) {
    __shared__ float As[16][64];
    __shared__ float Bs[16][64];
    int n0 = blockIdx.x * 64;
    int m0 = blockIdx.y * 64;
    int t = threadIdx.x;
    int tx = t & 15, ty = t >> 4;
    float acc[4][4];
    #pragma unroll
    for (int i = 0; i < 4; i++)
        #pragma unroll
        for (int j = 0; j < 4; j++) acc[i][j] = 0.f;
    for (int k0 = 0; k0 < K; k0 += 16) {
        {
            int row = t >> 2, kq = t & 3;
            float4 v = *(const float4*)(A + (size_t)(m0+row)*K + k0 + kq*4);
            As[kq*4+0][row] = v.x; As[kq*4+1][row] = v.y;
            As[kq*4+2][row] = v.z; As[kq*4+3][row] = v.w;
        }
        {
            int kk = t >> 4, nq = t & 15;
            *(float4*)&Bs[kk][nq*4] =
                *(const float4*)(Bm + (size_t)(k0+kk)*N + n0 + nq*4);
        }
        __syncthreads();
        #pragma unroll
        for (int kk = 0; kk < 16; kk++) {
            float a[4], b[4];
            #pragma unroll
            for (int i = 0; i < 4; i++) a[i] = As[kk][ty + i*16];
            #pragma unroll
            for (int j = 0; j < 4; j++) b[j] = Bs[kk][tx + j*16];
            #pragma unroll
            for (int i = 0; i < 4; i++)
                #pragma unroll
                for (int j = 0; j < 4; j++) acc[i][j] += a[i] * b[j];
        }
        __syncthreads();
    }
    #pragma unroll
    for (int i = 0; i < 4; i++) {
        int m = m0 + ty + i*16;
        #pragma unroll
        for (int j = 0; j < 4; j++) {
            int n = n0 + tx + j*16;
            float v = acc[i][j] + bias[n];
            if (RELU) v = fmaxf(v, 0.f);
            C[(size_t)m*N + n] = v;
        }
    }
}

// per-row: log_softmax stats, entropy, critic value, gumbel-argmax sample
__global__ __launch_bounds__(256) void k_final(
    const float* __restrict__ Wc, const float* __restrict__ bc,
    float* __restrict__ out) {
    int b_ = blockIdx.x;
    int t = threadIdx.x;
    __shared__ float sred[256];
    __shared__ float sgv[256];
    __shared__ int   sgi[256];
    const float* lrow = g_logits + (size_t)b_ * N_ACT;
    float l[4];
    #pragma unroll
    for (int k = 0; k < 4; k++) l[k] = lrow[t + k*256];

    float mx = fmaxf(fmaxf(l[0], l[1]), fmaxf(l[2], l[3]));
    sred[t] = mx; __syncthreads();
    for (int s = 128; s > 0; s >>= 1) {
        if (t < s) sred[t] = fmaxf(sred[t], sred[t+s]);
        __syncthreads();
    }
    mx = sred[0]; __syncthreads();

    float se = 0.f;
    #pragma unroll
    for (int k = 0; k < 4; k++) se += expf(l[k] - mx);
    sred[t] = se; __syncthreads();
    for (int s = 128; s > 0; s >>= 1) {
        if (t < s) sred[t] += sred[t+s];
        __syncthreads();
    }
    float lse = mx + logf(sred[0]); __syncthreads();

    float ent = 0.f;
    #pragma unroll
    for (int k = 0; k < 4; k++) {
        float lp = l[k] - lse;
        ent += expf(lp) * lp;
    }
    sred[t] = ent; __syncthreads();
    for (int s = 128; s > 0; s >>= 1) {
        if (t < s) sred[t] += sred[t+s];
        __syncthreads();
    }
    float entropy = -sred[0]; __syncthreads();

    const float* ha = g_ha + (size_t)b_ * A2C_H;
    float v = ha[t] * Wc[t] + ha[t + 256] * Wc[t + 256];
    sred[t] = v; __syncthreads();
    for (int s = 128; s > 0; s >>= 1) {
        if (t < s) sred[t] += sred[t+s];
        __syncthreads();
    }
    float vt = sred[0] + bc[0];

    float bv = -3.0e38f; int bn = 0;
    #pragma unroll
    for (int k = 0; k < 4; k++) {
        int n = t + k*256;
        float g = gumbel_at(b_ * N_ACT + n);
        float cand = (l[k] - lse) + g;
        if (cand > bv) { bv = cand; bn = n; }
    }
    sgv[t] = bv; sgi[t] = bn; __syncthreads();
    for (int s = 128; s > 0; s >>= 1) {
        if (t < s) {
            if (sgv[t+s] > sgv[t] || (sgv[t+s] == sgv[t] && sgi[t+s] < sgi[t])) {
                sgv[t] = sgv[t+s]; sgi[t] = sgi[t+s];
            }
        }
        __syncthreads();
    }
    if (t == 0) {
        int nbest = sgi[0];
        out[OFF_A + b_] = (float)nbest;
        out[OFF_PROB + b_] = lrow[nbest] - lse;
        out[OFF_V + b_] = vt;
        out[OFF_ENT + b_] = entropy;
    }
}

// last-write-wins scatter of q_t / c_t into the dict copies
__global__ __launch_bounds__(256) void k_scatter(
    const int* __restrict__ widx, const float* __restrict__ q,
    float* __restrict__ out) {
    int b_ = blockIdx.x;
    __shared__ int target;
    if (threadIdx.x == 0) {
        int idx = widx[b_];
        int last = 1;
        for (int b2 = b_ + 1; b2 < BB; b2++)
            if (widx[b2] == idx) { last = 0; break; }
        target = last ? idx : -1;
    }
    __syncthreads();
    int idx = target;
    if (idx < 0) return;
    int t = threadIdx.x;
    const float4* qs = (const float4*)(q + (size_t)b_ * KEY_DIM);
    const float4* cs = (const float4*)(out + OFF_C + (size_t)b_ * H);
    float4* kd = (float4*)(out + OFF_NK + (size_t)idx * KEY_DIM);
    float4* vd = (float4*)(out + OFF_NV + (size_t)idx * H);
    kd[t] = qs[t];
    vd[t] = cs[t];
}

extern "C" void kernel_launch(void* const* d_in, const int* in_sizes, int n_in,
                              void* d_out, int out_size) {
    const float* obs     = (const float*)d_in[0];
    const float* barcode = (const float*)d_in[1];
    const float* h_in    = (const float*)d_in[2];
    const float* c_in    = (const float*)d_in[3];
    const int*   widx    = (const int*)  d_in[4];
    const float* Wi      = (const float*)d_in[5];
    const float* bi      = (const float*)d_in[6];
    const float* Wh      = (const float*)d_in[7];
    const float* bh      = (const float*)d_in[8];
    const float* mk      = (const float*)d_in[9];
    const float* mv      = (const float*)d_in[10];
    const float* Wa      = (const float*)d_in[11];
    const float* ba      = (const float*)d_in[12];
    const float* Wact    = (const float*)d_in[13];
    const float* bact    = (const float*)d_in[14];
    const float* Wc      = (const float*)d_in[15];
    const float* bc      = (const float*)d_in[16];
    float* out = (float*)d_out;

    float* g_ha_ptr; cudaGetSymbolAddress((void**)&g_ha_ptr, g_ha);
    float* g_logits_ptr; cudaGetSymbolAddress((void**)&g_logits_ptr, g_logits);

    // one-time resources (no device memory): side streams + fork/join events
    static cudaStream_t s2 = nullptr, s3 = nullptr;
    static cudaEvent_t e0 = nullptr, eA = nullptr, eP = nullptr, eC = nullptr;
    if (!s2) {
        cudaStreamCreateWithFlags(&s2, cudaStreamNonBlocking);
        cudaStreamCreateWithFlags(&s3, cudaStreamNonBlocking);
        cudaEventCreateWithFlags(&e0, cudaEventDisableTiming);
        cudaEventCreateWithFlags(&eA, cudaEventDisableTiming);
        cudaEventCreateWithFlags(&eP, cudaEventDisableTiming);
        cudaEventCreateWithFlags(&eC, cudaEventDisableTiming);
        cudaFuncSetAttribute(k_sims_mma, cudaFuncAttributeMaxDynamicSharedMemorySize,
                             SIMS_SMEM);
        cudaFuncSetAttribute(k_preact_mma, cudaFuncAttributeMaxDynamicSharedMemorySize,
                             PRE_SMEM);
    }

    cudaEventRecord(e0, 0);                       // fork root
    k_qprep<<<BB, 128>>>(barcode);                                    // #1
    k_asplit<<<BB*KTOT/256, 256>>>(obs, h_in);                        // #2
    cudaEventRecord(eA, 0);

    cudaStreamWaitEvent(s2, e0, 0);
    k_wtrans<<<dim3(KTOT/32, FIVE_H/32), dim3(32, 8), 0, s2>>>(Wi, Wh); // #3

    k_sims_mma<<<DICT_LEN/128, 512, SIMS_SMEM>>>(mk);                 // #4 (profiled)

    cudaStreamWaitEvent(s3, e0, 0);
    k_copy<<<DICT_LEN, 128, 0, s3>>>(mk, mv, out + OFF_NK, out + OFF_NV); // #5
    cudaEventRecord(eC, s3);

    cudaStreamWaitEvent(s2, eA, 0);
    k_preact_mma<<<dim3(FIVE_H/128, BB/64), 256, PRE_SMEM, s2>>>(bi, bh); // #6
    cudaEventRecord(eP, s2);

    k_finalmax<<<BB, 128>>>();                                        // #7
    cudaStreamWaitEvent(0, eP, 0);
    k_lstm<<<BB*H/256, 256>>>(c_in, mv, out);                         // #8
    cudaStreamWaitEvent(0, eC, 0);
    k_scatter<<<BB, 256>>>(widx, barcode, out);                       // #9
    // ha = relu(c_t @ Wa + ba)
    k_gemm<1><<<dim3(A2C_H/64, BB/64), 256>>>(out + OFF_C, Wa, ba, g_ha_ptr,
                                              BB, A2C_H, H);          // #10
    // logits = ha @ W_actor + b_actor
    k_gemm<0><<<dim3(N_ACT/64, BB/64), 256>>>(g_ha_ptr, Wact, bact, g_logits_ptr,
                                              BB, N_ACT, A2C_H);      // #11
    k_final<<<BB, 256>>>(Wc, bc, out);                                // #12
}